// round 3
// baseline (speedup 1.0000x reference)
#include <cuda_runtime.h>

#define HH 56
#define WW 56
#define HW 3136
#define NB 16
#define NFM 32
#define NC 128

// ---------------- device scratch (no allocation allowed) ----------------
__device__ float g_Ab[NB * NC * HW];       // relu(tile(symm_pad(A)) + 0.1*noise)
__device__ float g_sum[NB * NC];           // per-(b,c) spatial sums
__device__ int   g_fmidx[NB * NFM];        // winning channel per (b, fm)
__device__ float g_Kch[NC * NC * 25];      // K_change accumulator (unscaled sums)
__device__ float g_W2[NC * NC * 25];       // final normalized conv weights [o][i][25]

// symm_pad(x, 2) on 56: index map (rows/cols compose separably)
__device__ __forceinline__ int map2i(int i) { return i < 2 ? 3 - i : (i >= 54 ? 107 - i : i); }
// pad_activations: 60x60 padded index -> 56 source index (no zeros survive)
__device__ __forceinline__ int mPad(int i) { return i < 4 ? 5 - i : (i < 56 ? i - 2 : 109 - i); }

__device__ __forceinline__ void cp8(unsigned dst, const float* src) {
    asm volatile("cp.async.ca.shared.global [%0], [%1], 8;" ::
                 "r"(dst), "l"(__cvta_generic_to_global(src)));
}
__device__ __forceinline__ void cp_commit() { asm volatile("cp.async.commit_group;"); }
__device__ __forceinline__ void cp_wait0()  { asm volatile("cp.async.wait_group 0;" ::: "memory"); }

// ---------------- kernel 0: zero K_change accumulator ----------------
__global__ void k_zero() {
    g_Kch[blockIdx.x * 1024 + threadIdx.x] = 0.0f;
}

// ---------------- kernel 1: build Ab + per-map sums ----------------
__global__ __launch_bounds__(256) void k_ab(const float* __restrict__ A,
                                            const float* __restrict__ noise) {
    int bc = blockIdx.x;             // b*128 + c
    int b = bc >> 7, c = bc & 127, fm = c & 31;
    const float* aB = A + (b * NFM + fm) * HW;
    const float* nB = noise + bc * HW;
    float* oB = g_Ab + bc * HW;
    float s = 0.0f;
    for (int p = threadIdx.x; p < HW; p += 256) {
        int h = p / WW, w = p - h * WW;
        float v = aB[map2i(h) * WW + map2i(w)] + 0.1f * nB[p];
        v = fmaxf(v, 0.0f);
        oB[p] = v;
        s += v;
    }
    #pragma unroll
    for (int o = 16; o; o >>= 1) s += __shfl_xor_sync(0xffffffffu, s, o);
    __shared__ float red[8];
    if ((threadIdx.x & 31) == 0) red[threadIdx.x >> 5] = s;
    __syncthreads();
    if (threadIdx.x == 0) {
        float t = 0.0f;
        #pragma unroll
        for (int i = 0; i < 8; i++) t += red[i];
        g_sum[bc] = t;
    }
}

// ---------------- kernel 2: winners (softmax map sums to 1 -> argmax of sum(Ab)) ----------------
__global__ void k_winners() {
    int t = threadIdx.x;
    if (t >= NB * NFM) return;
    int b = t >> 5, fm = t & 31;
    const float* s = g_sum + b * NC;
    float best = s[fm];
    int wi = 0;
    #pragma unroll
    for (int r = 1; r < 4; r++) {
        float v = s[r * NFM + fm];
        if (v > best) { best = v; wi = r; }   // strict > = first-max, like jnp.argmax
    }
    g_fmidx[t] = wi * NFM + fm;
}

// ---------------- kernel 3: K_change correlation ----------------
// K_change[c,a,x,y] += sum_{h,w} Am[b,c,h,w] * Abzp[b,a, h-x+2, w-y+2] (zero outside)
// Block = (winner index j, batch b). 5 warps; warp = x offset. Ab double-buffered via cp.async.
__global__ __launch_bounds__(160) void k_kchange() {
    __shared__ __align__(16) float sAm[HW];
    __shared__ __align__(16) float sAb[2][3600];   // 60x60, data at [r+2][w+2], halo = 0
    int j = blockIdx.x, b = blockIdx.y, tid = threadIdx.x;
    int c = g_fmidx[b * NFM + j];
    const float* amG = g_Ab + (b * NC + c) * HW;
    for (int p = tid; p < HW; p += 160) sAm[p] = amG[p];
    for (int p = tid; p < 7200; p += 160) ((float*)sAb)[p] = 0.0f;  // halos stay 0 forever
    __syncthreads();
    unsigned sb0 = (unsigned)__cvta_generic_to_shared(&sAb[0][0]);
    unsigned sb1 = (unsigned)__cvta_generic_to_shared(&sAb[1][0]);
    const float* abBase = g_Ab + (b * NC) * HW;
    {   // preload a = 0 (56 rows x 28 eight-byte chunks)
        const float* src = abBase;
        for (int i2 = tid; i2 < 1568; i2 += 160) {
            int r = i2 / 28, k = i2 - r * 28;
            cp8(sb0 + (unsigned)(((r + 2) * 60 + 2 + 2 * k) * 4), src + r * WW + 2 * k);
        }
        cp_commit();
    }
    int x = tid >> 5, lane = tid & 31;
    float* kdst = g_Kch + c * NC * 25 + x * 5;
    for (int a = 0; a < NC; a++) {
        cp_wait0();
        __syncthreads();                 // buffer (a&1) ready; other buffer free
        if (a + 1 < NC) {
            const float* src = abBase + (a + 1) * HW;
            unsigned d = ((a + 1) & 1) ? sb1 : sb0;
            for (int i2 = tid; i2 < 1568; i2 += 160) {
                int r = i2 / 28, k = i2 - r * 28;
                cp8(d + (unsigned)(((r + 2) * 60 + 2 + 2 * k) * 4), src + r * WW + 2 * k);
            }
            cp_commit();
        }
        const float* ab = sAb[a & 1];
        float acc[5] = {0.f, 0.f, 0.f, 0.f, 0.f};
        for (int it = lane; it < 392; it += 32) {       // 56 rows x 7 eight-pixel segs
            int h = it / 7, w0 = (it - h * 7) * 8;
            const float4* amp = (const float4*)(sAm + h * WW + w0);
            float4 A0 = amp[0], A1 = amp[1];
            float am[8] = {A0.x, A0.y, A0.z, A0.w, A1.x, A1.y, A1.z, A1.w};
            const float4* abp = (const float4*)(ab + (h - x + 4) * 60 + w0);
            float4 B0 = abp[0], B1 = abp[1], B2 = abp[2];
            float av[12] = {B0.x, B0.y, B0.z, B0.w, B1.x, B1.y, B1.z, B1.w,
                            B2.x, B2.y, B2.z, B2.w};
            #pragma unroll
            for (int y = 0; y < 5; y++) {
                #pragma unroll
                for (int t = 0; t < 8; t++) acc[y] += am[t] * av[t + 4 - y];
            }
        }
        #pragma unroll
        for (int y = 0; y < 5; y++) {
            float v = acc[y];
            #pragma unroll
            for (int o = 16; o; o >>= 1) v += __shfl_xor_sync(0xffffffffu, v, o);
            if (lane == 0) atomicAdd(kdst + a * 25 + y, v);
        }
    }
}

// ---------------- kernel 4: W2[o][i] = minmax( 0.9*K[o,i] + 0.1*minmax(Kch[i,o]/2048) ) ----------------
__global__ __launch_bounds__(256) void k_combine(const float* __restrict__ K) {
    int t = blockIdx.x * 256 + threadIdx.x;   // t = o*128 + i
    int o = t >> 7, i = t & 127;
    const float* kc = g_Kch + (i * NC + o) * 25;
    const float* kk = K + (o * NC + i) * 25;
    float v[25];
    float mn = 1e30f, mx = -1e30f;
    #pragma unroll
    for (int s = 0; s < 25; s++) {
        v[s] = kc[s] * (1.0f / 2048.0f);      // / (C*B)
        mn = fminf(mn, v[s]); mx = fmaxf(mx, v[s]);
    }
    float inv = 1.0f / (mx - mn + 1e-10f);
    float mn2 = 1e30f, mx2 = -1e30f;
    #pragma unroll
    for (int s = 0; s < 25; s++) {
        v[s] = 0.9f * kk[s] + 0.1f * ((v[s] - mn) * inv);
        mn2 = fminf(mn2, v[s]); mx2 = fmaxf(mx2, v[s]);
    }
    float inv2 = 1.0f / (mx2 - mn2 + 1e-10f);
    float* dst = g_W2 + (o * NC + i) * 25;
    #pragma unroll
    for (int s = 0; s < 25; s++) dst[s] = (v[s] - mn2) * inv2;
}

// ---------------- kernel 5: L2 conv (32 winners in, gathered out) + output ----------------
// O[b,fm,h,w] = Ab[b,o,h,w] + 0.1 * (1/32) * sum_{i in winners} conv5x5(pad(Ab[b,i]), W2[o,i])
// with o = fm_idx[b,fm]. Block = (fm, b); 224 threads, each owns a 1x14 strip.
__global__ __launch_bounds__(224) void k_l2out(float* __restrict__ out) {
    __shared__ float sIn[3600];   // padded 60x60 input channel
    __shared__ float sW[25];
    __shared__ int wl[32];
    int b = blockIdx.y, fm = blockIdx.x, tid = threadIdx.x;
    if (tid < 32) wl[tid] = g_fmidx[b * NFM + tid];
    __syncthreads();
    int o = wl[fm];
    int h = tid >> 2, w0 = (tid & 3) * 14;
    float acc[14];
    #pragma unroll
    for (int q = 0; q < 14; q++) acc[q] = 0.0f;
    for (int ii = 0; ii < 32; ii++) {
        int i = wl[ii];
        const float* src = g_Ab + (b * NC + i) * HW;
        __syncthreads();
        for (int p = tid; p < 3600; p += 224) {
            int r = p / 60, s = p - r * 60;
            sIn[p] = src[mPad(r) * WW + mPad(s)];
        }
        if (tid < 25) sW[tid] = g_W2[(o * NC + i) * 25 + tid];
        __syncthreads();
        float wk[25];
        #pragma unroll
        for (int s = 0; s < 25; s++) wk[s] = sW[s];
        #pragma unroll
        for (int kx = 0; kx < 5; kx++) {
            const float* rp = sIn + (h + kx) * 60 + w0;
            float rb[18];
            #pragma unroll
            for (int t = 0; t < 18; t++) rb[t] = rp[t];
            #pragma unroll
            for (int ky = 0; ky < 5; ky++) {
                float wv = wk[kx * 5 + ky];
                #pragma unroll
                for (int q = 0; q < 14; q++) acc[q] += rb[q + ky] * wv;
            }
        }
    }
    const float* abo = g_Ab + (b * NC + o) * HW;
    float* op = out + (b * NFM + fm) * HW;
    #pragma unroll
    for (int q = 0; q < 14; q++) {
        int p = h * WW + w0 + q;
        op[p] = abo[p] + 0.1f * acc[q] * (1.0f / 32.0f);
    }
}

extern "C" void kernel_launch(void* const* d_in, const int* in_sizes, int n_in,
                              void* d_out, int out_size) {
    const float* A     = (const float*)d_in[0];
    const float* K     = (const float*)d_in[1];
    const float* noise = (const float*)d_in[2];
    float* out = (float*)d_out;

    k_zero<<<400, 1024>>>();
    k_ab<<<2048, 256>>>(A, noise);
    k_winners<<<1, 512>>>();
    k_kchange<<<dim3(32, 16), 160>>>();
    k_combine<<<64, 256>>>(K);
    k_l2out<<<dim3(32, 16), 224>>>(out);
}

// round 4
// speedup vs baseline: 1.6512x; 1.6512x over previous
#include <cuda_runtime.h>

#define HH 56
#define WW 56
#define HW 3136
#define NB 16
#define NFM 32
#define NC 128

// ---------------- device scratch ----------------
__device__ float g_Ab[NB * NC * HW];
__device__ float g_sum[NB * NC];
__device__ int   g_fmidx[NB * NFM];
__device__ float g_Kch[NC * NC * 25];
__device__ float g_W2[NC * NC * 25];

__device__ __forceinline__ int map2i(int i) { return i < 2 ? 3 - i : (i >= 54 ? 107 - i : i); }
__device__ __forceinline__ int mPad(int i)  { return i < 4 ? 5 - i : (i < 56 ? i - 2 : 109 - i); }

__device__ __forceinline__ void cp8(unsigned dst, const float* src) {
    asm volatile("cp.async.ca.shared.global [%0], [%1], 8;" ::
                 "r"(dst), "l"(__cvta_generic_to_global(src)));
}
__device__ __forceinline__ void cp_commit() { asm volatile("cp.async.commit_group;"); }
__device__ __forceinline__ void cp_wait0()  { asm volatile("cp.async.wait_group 0;" ::: "memory"); }

__device__ __forceinline__ unsigned long long bcast2(float v) {
    unsigned long long r;
    asm("mov.b64 %0, {%1, %1};" : "=l"(r) : "f"(v));
    return r;
}
__device__ __forceinline__ void ffma2(unsigned long long& d, unsigned long long a,
                                      unsigned long long b) {
    asm("fma.rn.f32x2 %0, %1, %2, %0;" : "+l"(d) : "l"(a), "l"(b));
}
__device__ __forceinline__ void unpack2(unsigned long long v, float& lo, float& hi) {
    asm("mov.b64 {%0, %1}, %2;" : "=f"(lo), "=f"(hi) : "l"(v));
}

// ---------------- kernel 0: zero K_change ----------------
__global__ void k_zero() { g_Kch[blockIdx.x * 1024 + threadIdx.x] = 0.0f; }

// ---------------- kernel 1: Ab + per-map sums ----------------
__global__ __launch_bounds__(256) void k_ab(const float* __restrict__ A,
                                            const float* __restrict__ noise) {
    int bc = blockIdx.x;
    int b = bc >> 7, c = bc & 127, fm = c & 31;
    const float* aB = A + (b * NFM + fm) * HW;
    const float* nB = noise + bc * HW;
    float* oB = g_Ab + bc * HW;
    float s = 0.0f;
    for (int p = threadIdx.x; p < HW; p += 256) {
        int h = p / WW, w = p - h * WW;
        float v = aB[map2i(h) * WW + map2i(w)] + 0.1f * nB[p];
        v = fmaxf(v, 0.0f);
        oB[p] = v;
        s += v;
    }
    #pragma unroll
    for (int o = 16; o; o >>= 1) s += __shfl_xor_sync(0xffffffffu, s, o);
    __shared__ float red[8];
    if ((threadIdx.x & 31) == 0) red[threadIdx.x >> 5] = s;
    __syncthreads();
    if (threadIdx.x == 0) {
        float t = 0.0f;
        #pragma unroll
        for (int i = 0; i < 8; i++) t += red[i];
        g_sum[bc] = t;
    }
}

// ---------------- kernel 2: winners ----------------
__global__ void k_winners() {
    int t = threadIdx.x;
    if (t >= NB * NFM) return;
    int b = t >> 5, fm = t & 31;
    const float* s = g_sum + b * NC;
    float best = s[fm];
    int wi = 0;
    #pragma unroll
    for (int r = 1; r < 4; r++) {
        float v = s[r * NFM + fm];
        if (v > best) { best = v; wi = r; }
    }
    g_fmidx[t] = wi * NFM + fm;
}

// ---------------- kernel 3: K_change (c-tile=4, swizzled interleave, f32x2) ----------------
// Block: (jg in 0..7 winner-group, b, az in 0..3). 160 threads, 5 warps, warp = x offset.
// smem: sAmI = 3136 x float4 (channels interleaved, XOR-swizzled), sAb = 2 x 3600 (60x60 zero-halo)
#define SAMI_FLTS 12544
#define KCH_SMEM  ((SAMI_FLTS + 7200) * 4)
__global__ __launch_bounds__(160) void k_kchange() {
    extern __shared__ __align__(16) float dyn[];
    float* sAmI = dyn;                  // [3136] float4
    float* sAb  = dyn + SAMI_FLTS;      // [2][3600]
    int jg = blockIdx.x, b = blockIdx.y, a0 = blockIdx.z * 32;
    int tid = threadIdx.x;
    int cw0 = g_fmidx[b * NFM + jg * 4 + 0];
    int cw1 = g_fmidx[b * NFM + jg * 4 + 1];
    int cw2 = g_fmidx[b * NFM + jg * 4 + 2];
    int cw3 = g_fmidx[b * NFM + jg * 4 + 3];
    const float* abBase = g_Ab + (size_t)(b * NC) * HW;
    const float* am0 = abBase + (size_t)cw0 * HW;
    const float* am1 = abBase + (size_t)cw1 * HW;
    const float* am2 = abBase + (size_t)cw2 * HW;
    const float* am3 = abBase + (size_t)cw3 * HW;
    // interleave + swizzle Am (4 channels per pixel)
    float4* amI4 = (float4*)sAmI;
    for (int p = tid; p < HW; p += 160) {
        int phys = p ^ ((p >> 3) & 7);
        amI4[phys] = make_float4(am0[p], am1[p], am2[p], am3[p]);
    }
    for (int p = tid; p < 7200; p += 160) sAb[p] = 0.0f;   // halos stay zero
    __syncthreads();
    unsigned sb0 = (unsigned)__cvta_generic_to_shared(sAb);
    unsigned sb1 = (unsigned)__cvta_generic_to_shared(sAb + 3600);
    {   // preload a0
        const float* src = abBase + (size_t)a0 * HW;
        for (int i2 = tid; i2 < 1568; i2 += 160) {
            int r = (i2 * 2341) >> 16, k = i2 - r * 28;
            cp8(sb0 + (unsigned)(((r + 2) * 60 + 2 + 2 * k) * 4), src + r * WW + 2 * k);
        }
        cp_commit();
    }
    int x = tid >> 5, lane = tid & 31;
    const ulonglong2* amq = (const ulonglong2*)sAmI;
    for (int a = a0; a < a0 + 32; a++) {
        cp_wait0();
        __syncthreads();
        if (a + 1 < a0 + 32) {
            const float* src = abBase + (size_t)(a + 1) * HW;
            unsigned d = ((a + 1) & 1) ? sb1 : sb0;
            for (int i2 = tid; i2 < 1568; i2 += 160) {
                int r = (i2 * 2341) >> 16, k = i2 - r * 28;
                cp8(d + (unsigned)(((r + 2) * 60 + 2 + 2 * k) * 4), src + r * WW + 2 * k);
            }
            cp_commit();
        }
        const float* ab = sAb + (a & 1) * 3600;
        unsigned long long acc01[5] = {0, 0, 0, 0, 0};
        unsigned long long acc23[5] = {0, 0, 0, 0, 0};
        for (int it = lane; it < 392; it += 32) {          // 56 rows x 7 segments of 8 px
            int h = (it * 9363) >> 16;                     // it / 7
            int k = it - h * 7, w0 = k * 8;
            int sx = it & 7;
            ulonglong2 amv[8];
            int qb = it << 3;
            #pragma unroll
            for (int t = 0; t < 8; t++) amv[t] = amq[qb + (t ^ sx)];
            const float4* abp = (const float4*)(ab + (h - x + 4) * 60 + w0);
            float4 B0 = abp[0], B1 = abp[1], B2 = abp[2];
            unsigned long long bv[12] = {
                bcast2(B0.x), bcast2(B0.y), bcast2(B0.z), bcast2(B0.w),
                bcast2(B1.x), bcast2(B1.y), bcast2(B1.z), bcast2(B1.w),
                bcast2(B2.x), bcast2(B2.y), bcast2(B2.z), bcast2(B2.w)};
            #pragma unroll
            for (int y = 0; y < 5; y++) {
                #pragma unroll
                for (int t = 0; t < 8; t++) {
                    ffma2(acc01[y], amv[t].x, bv[t + 4 - y]);
                    ffma2(acc23[y], amv[t].y, bv[t + 4 - y]);
                }
            }
        }
        #pragma unroll
        for (int y = 0; y < 5; y++) {
            float r0, r1, r2, r3;
            unpack2(acc01[y], r0, r1);
            unpack2(acc23[y], r2, r3);
            #pragma unroll
            for (int o = 16; o; o >>= 1) {
                r0 += __shfl_xor_sync(0xffffffffu, r0, o);
                r1 += __shfl_xor_sync(0xffffffffu, r1, o);
                r2 += __shfl_xor_sync(0xffffffffu, r2, o);
                r3 += __shfl_xor_sync(0xffffffffu, r3, o);
            }
            if (lane == 0) {
                int off = a * 25 + x * 5 + y;
                atomicAdd(g_Kch + cw0 * (NC * 25) + off, r0);
                atomicAdd(g_Kch + cw1 * (NC * 25) + off, r1);
                atomicAdd(g_Kch + cw2 * (NC * 25) + off, r2);
                atomicAdd(g_Kch + cw3 * (NC * 25) + off, r3);
            }
        }
    }
}

// ---------------- kernel 4: combine weights ----------------
__global__ __launch_bounds__(256) void k_combine(const float* __restrict__ K) {
    int t = blockIdx.x * 256 + threadIdx.x;
    int o = t >> 7, i = t & 127;
    const float* kc = g_Kch + (i * NC + o) * 25;
    const float* kk = K + (o * NC + i) * 25;
    float v[25];
    float mn = 1e30f, mx = -1e30f;
    #pragma unroll
    for (int s = 0; s < 25; s++) {
        v[s] = kc[s] * (1.0f / 2048.0f);
        mn = fminf(mn, v[s]); mx = fmaxf(mx, v[s]);
    }
    float inv = 1.0f / (mx - mn + 1e-10f);
    float mn2 = 1e30f, mx2 = -1e30f;
    #pragma unroll
    for (int s = 0; s < 25; s++) {
        v[s] = 0.9f * kk[s] + 0.1f * ((v[s] - mn) * inv);
        mn2 = fminf(mn2, v[s]); mx2 = fmaxf(mx2, v[s]);
    }
    float inv2 = 1.0f / (mx2 - mn2 + 1e-10f);
    float* dst = g_W2 + (o * NC + i) * 25;
    #pragma unroll
    for (int s = 0; s < 25; s++) dst[s] = (v[s] - mn2) * inv2;
}

// ---------------- kernel 5: L2 conv + output ----------------
__global__ __launch_bounds__(224) void k_l2out(float* __restrict__ out) {
    __shared__ float sIn[3600];
    __shared__ float sW[25];
    __shared__ int wl[32];
    int b = blockIdx.y, fm = blockIdx.x, tid = threadIdx.x;
    if (tid < 32) wl[tid] = g_fmidx[b * NFM + tid];
    __syncthreads();
    int o = wl[fm];
    int h = tid >> 2, w0 = (tid & 3) * 14;
    float acc[14];
    #pragma unroll
    for (int q = 0; q < 14; q++) acc[q] = 0.0f;
    for (int ii = 0; ii < 32; ii++) {
        int i = wl[ii];
        const float* src = g_Ab + (b * NC + i) * HW;
        __syncthreads();
        for (int p = tid; p < 3600; p += 224) {
            int r = p / 60, s = p - r * 60;
            sIn[p] = src[mPad(r) * WW + mPad(s)];
        }
        if (tid < 25) sW[tid] = g_W2[(o * NC + i) * 25 + tid];
        __syncthreads();
        float wk[25];
        #pragma unroll
        for (int s = 0; s < 25; s++) wk[s] = sW[s];
        #pragma unroll
        for (int kx = 0; kx < 5; kx++) {
            const float* rp = sIn + (h + kx) * 60 + w0;
            float rb[18];
            #pragma unroll
            for (int t = 0; t < 18; t++) rb[t] = rp[t];
            #pragma unroll
            for (int ky = 0; ky < 5; ky++) {
                float wv = wk[kx * 5 + ky];
                #pragma unroll
                for (int q = 0; q < 14; q++) acc[q] += rb[q + ky] * wv;
            }
        }
    }
    const float* abo = g_Ab + (b * NC + o) * HW;
    float* op = out + (b * NFM + fm) * HW;
    #pragma unroll
    for (int q = 0; q < 14; q++) {
        int p = h * WW + w0 + q;
        op[p] = abo[p] + 0.1f * acc[q] * (1.0f / 32.0f);
    }
}

extern "C" void kernel_launch(void* const* d_in, const int* in_sizes, int n_in,
                              void* d_out, int out_size) {
    const float* A     = (const float*)d_in[0];
    const float* K     = (const float*)d_in[1];
    const float* noise = (const float*)d_in[2];
    float* out = (float*)d_out;

    cudaFuncSetAttribute(k_kchange, cudaFuncAttributeMaxDynamicSharedMemorySize, KCH_SMEM);

    k_zero<<<400, 1024>>>();
    k_ab<<<2048, 256>>>(A, noise);
    k_winners<<<1, 512>>>();
    k_kchange<<<dim3(8, 16, 4), 160, KCH_SMEM>>>();
    k_combine<<<64, 256>>>(K);
    k_l2out<<<dim3(32, 16), 224>>>(out);
}

// round 5
// speedup vs baseline: 1.7373x; 1.0522x over previous
#include <cuda_runtime.h>

#define HH 56
#define WW 56
#define HW 3136
#define NB 16
#define NFM 32
#define NC 128

// ---------------- device scratch ----------------
__device__ float g_Ab[NB * NC * HW];
__device__ float g_sum[NB * NC];
__device__ int   g_fmidx[NB * NFM];
__device__ float g_Kch[NC * NC * 25];
__device__ float g_W2[NC * NC * 25];

__device__ __forceinline__ int map2i(int i) { return i < 2 ? 3 - i : (i >= 54 ? 107 - i : i); }
__device__ __forceinline__ int mPad(int i)  { return i < 4 ? 5 - i : (i < 56 ? i - 2 : 109 - i); }

__device__ __forceinline__ void cp8(unsigned dst, const float* src) {
    asm volatile("cp.async.ca.shared.global [%0], [%1], 8;" ::
                 "r"(dst), "l"(__cvta_generic_to_global(src)));
}
__device__ __forceinline__ void cp_commit() { asm volatile("cp.async.commit_group;"); }
__device__ __forceinline__ void cp_wait0()  { asm volatile("cp.async.wait_group 0;" ::: "memory"); }

__device__ __forceinline__ unsigned long long bcast2(float v) {
    unsigned long long r;
    asm("mov.b64 %0, {%1, %1};" : "=l"(r) : "f"(v));
    return r;
}
__device__ __forceinline__ unsigned long long pack2(float lo, float hi) {
    unsigned long long r;
    asm("mov.b64 %0, {%1, %2};" : "=l"(r) : "f"(lo), "f"(hi));
    return r;
}
__device__ __forceinline__ void ffma2(unsigned long long& d, unsigned long long a,
                                      unsigned long long b) {
    asm("fma.rn.f32x2 %0, %1, %2, %0;" : "+l"(d) : "l"(a), "l"(b));
}
__device__ __forceinline__ void unpack2(unsigned long long v, float& lo, float& hi) {
    asm("mov.b64 {%0, %1}, %2;" : "=f"(lo), "=f"(hi) : "l"(v));
}

// ---------------- kernel 0: zero K_change ----------------
__global__ void k_zero() { g_Kch[blockIdx.x * 1024 + threadIdx.x] = 0.0f; }

// ---------------- kernel 1: Ab + per-map sums ----------------
__global__ __launch_bounds__(256) void k_ab(const float* __restrict__ A,
                                            const float* __restrict__ noise) {
    int bc = blockIdx.x;
    int b = bc >> 7, c = bc & 127, fm = c & 31;
    const float* aB = A + (b * NFM + fm) * HW;
    const float* nB = noise + bc * HW;
    float* oB = g_Ab + bc * HW;
    float s = 0.0f;
    for (int p = threadIdx.x; p < HW; p += 256) {
        int h = p / WW, w = p - h * WW;
        float v = aB[map2i(h) * WW + map2i(w)] + 0.1f * nB[p];
        v = fmaxf(v, 0.0f);
        oB[p] = v;
        s += v;
    }
    #pragma unroll
    for (int o = 16; o; o >>= 1) s += __shfl_xor_sync(0xffffffffu, s, o);
    __shared__ float red[8];
    if ((threadIdx.x & 31) == 0) red[threadIdx.x >> 5] = s;
    __syncthreads();
    if (threadIdx.x == 0) {
        float t = 0.0f;
        #pragma unroll
        for (int i = 0; i < 8; i++) t += red[i];
        g_sum[bc] = t;
    }
}

// ---------------- kernel 2: winners ----------------
__global__ void k_winners() {
    int t = threadIdx.x;
    if (t >= NB * NFM) return;
    int b = t >> 5, fm = t & 31;
    const float* s = g_sum + b * NC;
    float best = s[fm];
    int wi = 0;
    #pragma unroll
    for (int r = 1; r < 4; r++) {
        float v = s[r * NFM + fm];
        if (v > best) { best = v; wi = r; }
    }
    g_fmidx[t] = wi * NFM + fm;
}

// ---------------- kernel 3: K_change (c-tile=4, swizzled interleave, f32x2, 10 warps) ----------------
// Block: (jg 0..7, b, az 0..7 -> 16 a-channels). 320 threads; warp = (x = wid>>1, half = wid&1).
#define SAMI_FLTS 12544
#define KCH_SMEM  ((SAMI_FLTS + 7200) * 4)
__global__ __launch_bounds__(320) void k_kchange() {
    extern __shared__ __align__(16) float dyn[];
    float* sAmI = dyn;                  // [3136] float4, channel-interleaved, XOR-swizzled
    float* sAb  = dyn + SAMI_FLTS;      // [2][3600] zero-halo 60x60
    int jg = blockIdx.x, b = blockIdx.y, a0 = blockIdx.z * 16;
    int tid = threadIdx.x;
    int cw0 = g_fmidx[b * NFM + jg * 4 + 0];
    int cw1 = g_fmidx[b * NFM + jg * 4 + 1];
    int cw2 = g_fmidx[b * NFM + jg * 4 + 2];
    int cw3 = g_fmidx[b * NFM + jg * 4 + 3];
    const float* abBase = g_Ab + (size_t)(b * NC) * HW;
    const float* am0 = abBase + (size_t)cw0 * HW;
    const float* am1 = abBase + (size_t)cw1 * HW;
    const float* am2 = abBase + (size_t)cw2 * HW;
    const float* am3 = abBase + (size_t)cw3 * HW;
    float4* amI4 = (float4*)sAmI;
    for (int p = tid; p < HW; p += 320) {
        int phys = p ^ ((p >> 3) & 7);
        amI4[phys] = make_float4(am0[p], am1[p], am2[p], am3[p]);
    }
    for (int p = tid; p < 7200; p += 320) sAb[p] = 0.0f;   // halos stay zero
    __syncthreads();
    unsigned sb0 = (unsigned)__cvta_generic_to_shared(sAb);
    unsigned sb1 = (unsigned)__cvta_generic_to_shared(sAb + 3600);
    {   // preload a0
        const float* src = abBase + (size_t)a0 * HW;
        for (int i2 = tid; i2 < 1568; i2 += 320) {
            int r = (i2 * 2341) >> 16, k = i2 - r * 28;
            cp8(sb0 + (unsigned)(((r + 2) * 60 + 2 + 2 * k) * 4), src + r * WW + 2 * k);
        }
        cp_commit();
    }
    int wid = tid >> 5, lane = tid & 31;
    int x = wid >> 1, half = wid & 1;
    int itBeg = half * 196 + lane, itEnd = (half + 1) * 196;
    const ulonglong2* amq = (const ulonglong2*)sAmI;
    for (int a = a0; a < a0 + 16; a++) {
        cp_wait0();
        __syncthreads();
        if (a + 1 < a0 + 16) {
            const float* src = abBase + (size_t)(a + 1) * HW;
            unsigned d = ((a + 1) & 1) ? sb1 : sb0;
            for (int i2 = tid; i2 < 1568; i2 += 320) {
                int r = (i2 * 2341) >> 16, k = i2 - r * 28;
                cp8(d + (unsigned)(((r + 2) * 60 + 2 + 2 * k) * 4), src + r * WW + 2 * k);
            }
            cp_commit();
        }
        const float* ab = sAb + (a & 1) * 3600;
        unsigned long long acc01[5] = {0, 0, 0, 0, 0};
        unsigned long long acc23[5] = {0, 0, 0, 0, 0};
        for (int it = itBeg; it < itEnd; it += 32) {       // 196 tiles per warp
            int h = (it * 9363) >> 16;                     // it / 7
            int k = it - h * 7, w0 = k * 8;
            int sx = it & 7;
            ulonglong2 amv[8];
            int qb = it << 3;
            #pragma unroll
            for (int t = 0; t < 8; t++) amv[t] = amq[qb + (t ^ sx)];
            const float4* abp = (const float4*)(ab + (h - x + 4) * 60 + w0);
            float4 B0 = abp[0], B1 = abp[1], B2 = abp[2];
            unsigned long long bv[12] = {
                bcast2(B0.x), bcast2(B0.y), bcast2(B0.z), bcast2(B0.w),
                bcast2(B1.x), bcast2(B1.y), bcast2(B1.z), bcast2(B1.w),
                bcast2(B2.x), bcast2(B2.y), bcast2(B2.z), bcast2(B2.w)};
            #pragma unroll
            for (int y = 0; y < 5; y++) {
                #pragma unroll
                for (int t = 0; t < 8; t++) {
                    ffma2(acc01[y], amv[t].x, bv[t + 4 - y]);
                    ffma2(acc23[y], amv[t].y, bv[t + 4 - y]);
                }
            }
        }
        #pragma unroll
        for (int y = 0; y < 5; y++) {
            float r0, r1, r2, r3;
            unpack2(acc01[y], r0, r1);
            unpack2(acc23[y], r2, r3);
            #pragma unroll
            for (int o = 16; o; o >>= 1) {
                r0 += __shfl_xor_sync(0xffffffffu, r0, o);
                r1 += __shfl_xor_sync(0xffffffffu, r1, o);
                r2 += __shfl_xor_sync(0xffffffffu, r2, o);
                r3 += __shfl_xor_sync(0xffffffffu, r3, o);
            }
            if (lane == 0) {
                int off = a * 25 + x * 5 + y;
                atomicAdd(g_Kch + cw0 * (NC * 25) + off, r0);
                atomicAdd(g_Kch + cw1 * (NC * 25) + off, r1);
                atomicAdd(g_Kch + cw2 * (NC * 25) + off, r2);
                atomicAdd(g_Kch + cw3 * (NC * 25) + off, r3);
            }
        }
    }
}

// ---------------- kernel 4: combine weights ----------------
__global__ __launch_bounds__(256) void k_combine(const float* __restrict__ K) {
    int t = blockIdx.x * 256 + threadIdx.x;
    int o = t >> 7, i = t & 127;
    const float* kc = g_Kch + (i * NC + o) * 25;
    const float* kk = K + (o * NC + i) * 25;
    float v[25];
    float mn = 1e30f, mx = -1e30f;
    #pragma unroll
    for (int s = 0; s < 25; s++) {
        v[s] = kc[s] * (1.0f / 2048.0f);
        mn = fminf(mn, v[s]); mx = fmaxf(mx, v[s]);
    }
    float inv = 1.0f / (mx - mn + 1e-10f);
    float mn2 = 1e30f, mx2 = -1e30f;
    #pragma unroll
    for (int s = 0; s < 25; s++) {
        v[s] = 0.9f * kk[s] + 0.1f * ((v[s] - mn) * inv);
        mn2 = fminf(mn2, v[s]); mx2 = fmaxf(mx2, v[s]);
    }
    float inv2 = 1.0f / (mx2 - mn2 + 1e-10f);
    float* dst = g_W2 + (o * NC + i) * 25;
    #pragma unroll
    for (int s = 0; s < 25; s++) dst[s] = (v[s] - mn2) * inv2;
}

// ---------------- kernel 5: L2 conv + output (f32x2 over q-pairs) ----------------
__global__ __launch_bounds__(224) void k_l2out(float* __restrict__ out) {
    __shared__ float sIn[3600];
    __shared__ float sW[25];
    __shared__ int wl[32];
    int b = blockIdx.y, fm = blockIdx.x, tid = threadIdx.x;
    if (tid < 32) wl[tid] = g_fmidx[b * NFM + tid];
    __syncthreads();
    int o = wl[fm];
    int h = tid >> 2, w0 = (tid & 3) * 14;
    unsigned long long accp[7] = {0, 0, 0, 0, 0, 0, 0};
    for (int ii = 0; ii < 32; ii++) {
        int i = wl[ii];
        const float* src = g_Ab + (b * NC + i) * HW;
        __syncthreads();
        for (int p = tid; p < 3600; p += 224) {
            int r = p / 60, s = p - r * 60;
            sIn[p] = src[mPad(r) * WW + mPad(s)];
        }
        if (tid < 25) sW[tid] = g_W2[(o * NC + i) * 25 + tid];
        __syncthreads();
        #pragma unroll
        for (int kx = 0; kx < 5; kx++) {
            const float* rp = sIn + (h + kx) * 60 + w0;
            float rb[18];
            #pragma unroll
            for (int t = 0; t < 18; t++) rb[t] = rp[t];
            unsigned long long rbe[9], rbo[8];
            #pragma unroll
            for (int t = 0; t < 9; t++) rbe[t] = pack2(rb[2 * t], rb[2 * t + 1]);
            #pragma unroll
            for (int t = 0; t < 8; t++) rbo[t] = pack2(rb[2 * t + 1], rb[2 * t + 2]);
            #pragma unroll
            for (int ky = 0; ky < 5; ky++) {
                unsigned long long wv2 = bcast2(sW[kx * 5 + ky]);
                int m = ky >> 1;
                if ((ky & 1) == 0) {
                    #pragma unroll
                    for (int qq = 0; qq < 7; qq++) ffma2(accp[qq], rbe[qq + m], wv2);
                } else {
                    #pragma unroll
                    for (int qq = 0; qq < 7; qq++) ffma2(accp[qq], rbo[qq + m], wv2);
                }
            }
        }
    }
    const float* abo = g_Ab + (b * NC + o) * HW;
    float* op = out + (b * NFM + fm) * HW;
    #pragma unroll
    for (int qq = 0; qq < 7; qq++) {
        float a0, a1;
        unpack2(accp[qq], a0, a1);
        int p = h * WW + w0 + 2 * qq;
        op[p]     = abo[p]     + 0.1f * a0 * (1.0f / 32.0f);
        op[p + 1] = abo[p + 1] + 0.1f * a1 * (1.0f / 32.0f);
    }
}

extern "C" void kernel_launch(void* const* d_in, const int* in_sizes, int n_in,
                              void* d_out, int out_size) {
    const float* A     = (const float*)d_in[0];
    const float* K     = (const float*)d_in[1];
    const float* noise = (const float*)d_in[2];
    float* out = (float*)d_out;

    cudaFuncSetAttribute(k_kchange, cudaFuncAttributeMaxDynamicSharedMemorySize, KCH_SMEM);

    k_zero<<<400, 1024>>>();
    k_ab<<<2048, 256>>>(A, noise);
    k_winners<<<1, 512>>>();
    k_kchange<<<dim3(8, 16, 8), 320, KCH_SMEM>>>();
    k_combine<<<64, 256>>>(K);
    k_l2out<<<dim3(32, 16), 224>>>(out);
}

// round 7
// speedup vs baseline: 1.8307x; 1.0537x over previous
#include <cuda_runtime.h>

#define HH 56
#define WW 56
#define HW 3136
#define NB 16
#define NFM 32
#define NC 128

// ---------------- device scratch ----------------
__device__ float g_Ab[NB * NC * HW];
__device__ float g_sum[NB * NC];
__device__ int   g_fmidx[NB * NFM];
__device__ float g_Kch[NC * NC * 25];
__device__ float g_W2[NC * NC * 25];
__device__ float g_Pad[NB][NFM][3600];   // padded (60x60) winner channels

__device__ __forceinline__ int map2i(int i) { return i < 2 ? 3 - i : (i >= 54 ? 107 - i : i); }
__device__ __forceinline__ int mPad(int i)  { return i < 4 ? 5 - i : (i < 56 ? i - 2 : 109 - i); }

__device__ __forceinline__ void cp8(unsigned dst, const float* src) {
    asm volatile("cp.async.ca.shared.global [%0], [%1], 8;" ::
                 "r"(dst), "l"(__cvta_generic_to_global(src)));
}
__device__ __forceinline__ void cp_commit() { asm volatile("cp.async.commit_group;"); }
__device__ __forceinline__ void cp_wait0()  { asm volatile("cp.async.wait_group 0;" ::: "memory"); }

__device__ __forceinline__ unsigned long long bcast2(float v) {
    unsigned long long r;
    asm("mov.b64 %0, {%1, %1};" : "=l"(r) : "f"(v));
    return r;
}
__device__ __forceinline__ unsigned long long pack2(float lo, float hi) {
    unsigned long long r;
    asm("mov.b64 %0, {%1, %2};" : "=l"(r) : "f"(lo), "f"(hi));
    return r;
}
__device__ __forceinline__ void ffma2(unsigned long long& d, unsigned long long a,
                                      unsigned long long b) {
    asm("fma.rn.f32x2 %0, %1, %2, %0;" : "+l"(d) : "l"(a), "l"(b));
}
__device__ __forceinline__ void fadd2(unsigned long long& d, unsigned long long a) {
    asm("add.rn.f32x2 %0, %0, %1;" : "+l"(d) : "l"(a));
}
__device__ __forceinline__ void unpack2(unsigned long long v, float& lo, float& hi) {
    asm("mov.b64 {%0, %1}, %2;" : "=f"(lo), "=f"(hi) : "l"(v));
}
// butterfly reduce a packed f32x2 pair across the warp (both halves independently)
__device__ __forceinline__ unsigned long long wred2(unsigned long long v) {
    #pragma unroll
    for (int m = 16; m; m >>= 1) {
        unsigned lo = (unsigned)v, hi = (unsigned)(v >> 32);
        lo = __shfl_xor_sync(0xffffffffu, lo, m);
        hi = __shfl_xor_sync(0xffffffffu, hi, m);
        fadd2(v, ((unsigned long long)hi << 32) | lo);
    }
    return v;
}

// ---------------- kernel 0: zero K_change ----------------
__global__ void k_zero() { g_Kch[blockIdx.x * 1024 + threadIdx.x] = 0.0f; }

// ---------------- kernel 1: Ab + per-map sums ----------------
__global__ __launch_bounds__(256) void k_ab(const float* __restrict__ A,
                                            const float* __restrict__ noise) {
    int bc = blockIdx.x;
    int b = bc >> 7, c = bc & 127, fm = c & 31;
    const float* aB = A + (b * NFM + fm) * HW;
    const float* nB = noise + bc * HW;
    float* oB = g_Ab + bc * HW;
    float s = 0.0f;
    for (int p = threadIdx.x; p < HW; p += 256) {
        int h = (p * 37450) >> 21;          // p / 56
        int w = p - h * WW;
        float v = aB[map2i(h) * WW + map2i(w)] + 0.1f * nB[p];
        v = fmaxf(v, 0.0f);
        oB[p] = v;
        s += v;
    }
    #pragma unroll
    for (int o = 16; o; o >>= 1) s += __shfl_xor_sync(0xffffffffu, s, o);
    __shared__ float red[8];
    if ((threadIdx.x & 31) == 0) red[threadIdx.x >> 5] = s;
    __syncthreads();
    if (threadIdx.x == 0) {
        float t = 0.0f;
        #pragma unroll
        for (int i = 0; i < 8; i++) t += red[i];
        g_sum[bc] = t;
    }
}

// ---------------- kernel 2: winners ----------------
__global__ void k_winners() {
    int t = threadIdx.x;
    if (t >= NB * NFM) return;
    int b = t >> 5, fm = t & 31;
    const float* s = g_sum + b * NC;
    float best = s[fm];
    int wi = 0;
    #pragma unroll
    for (int r = 1; r < 4; r++) {
        float v = s[r * NFM + fm];
        if (v > best) { best = v; wi = r; }
    }
    g_fmidx[t] = wi * NFM + fm;
}

// ---------------- kernel 2b: padded winner channels for l2out ----------------
__global__ __launch_bounds__(256) void k_pad() {
    int b = blockIdx.x, j = blockIdx.y;
    int c = g_fmidx[b * NFM + j];
    const float* src = g_Ab + (size_t)(b * NC + c) * HW;
    float* dst = &g_Pad[b][j][0];
    for (int p = threadIdx.x; p < 3600; p += 256) {
        int r = p / 60, s = p - r * 60;
        dst[p] = src[mPad(r) * WW + mPad(s)];
    }
}

// ---------------- kernel 3: K_change (c-tile=4, x-tile=2, packed reduction) ----------------
// Block: (jg 0..7, b, az 0..7 -> 16 a each). 320 threads.
// warps 0-3: x{0,1}; warps 4-7: x{2,3}; warps 8-9: x{4}. Equal FFMA2 per warp.
#define SAMI_FLTS 12544
#define KCH_SMEM  ((SAMI_FLTS + 7200) * 4)
__global__ __launch_bounds__(320, 2) void k_kchange() {
    extern __shared__ __align__(16) float dyn[];
    float* sAmI = dyn;                  // [3136] float4 interleaved + XOR swizzle
    float* sAb  = dyn + SAMI_FLTS;      // [2][3600] zero-halo 60x60
    int jg = blockIdx.x, b = blockIdx.y, a0 = blockIdx.z * 16;
    int tid = threadIdx.x;
    int cw0 = g_fmidx[b * NFM + jg * 4 + 0];
    int cw1 = g_fmidx[b * NFM + jg * 4 + 1];
    int cw2 = g_fmidx[b * NFM + jg * 4 + 2];
    int cw3 = g_fmidx[b * NFM + jg * 4 + 3];
    const float* abBase = g_Ab + (size_t)(b * NC) * HW;
    {
        const float* am0 = abBase + (size_t)cw0 * HW;
        const float* am1 = abBase + (size_t)cw1 * HW;
        const float* am2 = abBase + (size_t)cw2 * HW;
        const float* am3 = abBase + (size_t)cw3 * HW;
        float4* amI4 = (float4*)sAmI;
        for (int p = tid; p < HW; p += 320) {
            int phys = p ^ ((p >> 3) & 7);
            amI4[phys] = make_float4(am0[p], am1[p], am2[p], am3[p]);
        }
    }
    for (int p = tid; p < 7200; p += 320) sAb[p] = 0.0f;
    __syncthreads();
    unsigned sb0 = (unsigned)__cvta_generic_to_shared(sAb);
    unsigned sb1 = (unsigned)__cvta_generic_to_shared(sAb + 3600);
    {
        const float* src = abBase + (size_t)a0 * HW;
        for (int i2 = tid; i2 < 1568; i2 += 320) {
            int r = (i2 * 2341) >> 16, k = i2 - r * 28;
            cp8(sb0 + (unsigned)(((r + 2) * 60 + 2 + 2 * k) * 4), src + r * WW + 2 * k);
        }
        cp_commit();
    }
    int wid = tid >> 5, lane = tid & 31;
    const ulonglong2* amq = (const ulonglong2*)sAmI;
    float* kc0 = g_Kch + cw0 * 3200;
    float* kc1 = g_Kch + cw1 * 3200;
    float* kc2 = g_Kch + cw2 * 3200;
    float* kc3 = g_Kch + cw3 * 3200;
    for (int a = a0; a < a0 + 16; a++) {
        cp_wait0();
        __syncthreads();
        if (a + 1 < a0 + 16) {
            const float* src = abBase + (size_t)(a + 1) * HW;
            unsigned d = ((a + 1) & 1) ? sb1 : sb0;
            for (int i2 = tid; i2 < 1568; i2 += 320) {
                int r = (i2 * 2341) >> 16, k = i2 - r * 28;
                cp8(d + (unsigned)(((r + 2) * 60 + 2 + 2 * k) * 4), src + r * WW + 2 * k);
            }
            cp_commit();
        }
        const float* ab = sAb + (a & 1) * 3600;
        int sx = lane & 7;
        if (wid < 8) {
            // ---- two x offsets per warp ----
            int x0 = (wid >> 2) * 2;          // 0 or 2
            int w4 = wid & 3;
            unsigned long long acc[2][5][2];
            #pragma unroll
            for (int r = 0; r < 2; r++)
                #pragma unroll
                for (int y = 0; y < 5; y++) acc[r][y][0] = acc[r][y][1] = 0ull;
            for (int j = w4; j < 13; j += 4) {
                int it = j * 32 + lane;
                if (it < 392) {
                    int h = (it * 9363) >> 16;
                    int w0 = (it - h * 7) * 8;
                    ulonglong2 amv[8];
                    int qb = it << 3;
                    #pragma unroll
                    for (int t = 0; t < 8; t++) amv[t] = amq[qb + (t ^ sx)];
                    #pragma unroll
                    for (int r = 0; r < 2; r++) {
                        const float* rp = ab + (h + 4 - (x0 + r)) * 60 + w0;
                        unsigned long long bb[12];
                        #pragma unroll
                        for (int i = 0; i < 12; i++) bb[i] = bcast2(rp[i]);
                        #pragma unroll
                        for (int y = 0; y < 5; y++) {
                            #pragma unroll
                            for (int t = 0; t < 8; t++) {
                                ffma2(acc[r][y][0], amv[t].x, bb[t + 4 - y]);
                                ffma2(acc[r][y][1], amv[t].y, bb[t + 4 - y]);
                            }
                        }
                    }
                }
            }
            #pragma unroll
            for (int r = 0; r < 2; r++)
                #pragma unroll
                for (int y = 0; y < 5; y++) {
                    int off = a * 25 + (x0 + r) * 5 + y;
                    unsigned long long s01 = wred2(acc[r][y][0]);
                    unsigned long long s23 = wred2(acc[r][y][1]);
                    if (lane == 0) {
                        float v0, v1, v2, v3;
                        unpack2(s01, v0, v1);
                        unpack2(s23, v2, v3);
                        atomicAdd(kc0 + off, v0);
                        atomicAdd(kc1 + off, v1);
                        atomicAdd(kc2 + off, v2);
                        atomicAdd(kc3 + off, v3);
                    }
                }
        } else {
            // ---- single x = 4 ----
            int w2 = wid & 1;
            unsigned long long acc[5][2];
            #pragma unroll
            for (int y = 0; y < 5; y++) acc[y][0] = acc[y][1] = 0ull;
            for (int j = w2; j < 13; j += 2) {
                int it = j * 32 + lane;
                if (it < 392) {
                    int h = (it * 9363) >> 16;
                    int w0 = (it - h * 7) * 8;
                    ulonglong2 amv[8];
                    int qb = it << 3;
                    #pragma unroll
                    for (int t = 0; t < 8; t++) amv[t] = amq[qb + (t ^ sx)];
                    const float* rp = ab + h * 60 + w0;          // h + 4 - 4
                    unsigned long long bb[12];
                    #pragma unroll
                    for (int i = 0; i < 12; i++) bb[i] = bcast2(rp[i]);
                    #pragma unroll
                    for (int y = 0; y < 5; y++) {
                        #pragma unroll
                        for (int t = 0; t < 8; t++) {
                            ffma2(acc[y][0], amv[t].x, bb[t + 4 - y]);
                            ffma2(acc[y][1], amv[t].y, bb[t + 4 - y]);
                        }
                    }
                }
            }
            #pragma unroll
            for (int y = 0; y < 5; y++) {
                int off = a * 25 + 4 * 5 + y;
                unsigned long long s01 = wred2(acc[y][0]);
                unsigned long long s23 = wred2(acc[y][1]);
                if (lane == 0) {
                    float v0, v1, v2, v3;
                    unpack2(s01, v0, v1);
                    unpack2(s23, v2, v3);
                    atomicAdd(kc0 + off, v0);
                    atomicAdd(kc1 + off, v1);
                    atomicAdd(kc2 + off, v2);
                    atomicAdd(kc3 + off, v3);
                }
            }
        }
    }
}

// ---------------- kernel 4: combine weights ----------------
__global__ __launch_bounds__(256) void k_combine(const float* __restrict__ K) {
    int t = blockIdx.x * 256 + threadIdx.x;
    int o = t >> 7, i = t & 127;
    const float* kc = g_Kch + (i * NC + o) * 25;
    const float* kk = K + (o * NC + i) * 25;
    float v[25];
    float mn = 1e30f, mx = -1e30f;
    #pragma unroll
    for (int s = 0; s < 25; s++) {
        v[s] = kc[s] * (1.0f / 2048.0f);
        mn = fminf(mn, v[s]); mx = fmaxf(mx, v[s]);
    }
    float inv = 1.0f / (mx - mn + 1e-10f);
    float mn2 = 1e30f, mx2 = -1e30f;
    #pragma unroll
    for (int s = 0; s < 25; s++) {
        v[s] = 0.9f * kk[s] + 0.1f * ((v[s] - mn) * inv);
        mn2 = fminf(mn2, v[s]); mx2 = fmaxf(mx2, v[s]);
    }
    float inv2 = 1.0f / (mx2 - mn2 + 1e-10f);
    float* dst = g_W2 + (o * NC + i) * 25;
    #pragma unroll
    for (int s = 0; s < 25; s++) dst[s] = (v[s] - mn2) * inv2;
}

// ---------------- kernel 5: L2 conv + output (f32x2, streamed refill) ----------------
__global__ __launch_bounds__(224) void k_l2out(float* __restrict__ out) {
    __shared__ float sIn[3600];
    __shared__ float sW[25];
    __shared__ int wl[32];
    int b = blockIdx.y, fm = blockIdx.x, tid = threadIdx.x;
    if (tid < 32) wl[tid] = g_fmidx[b * NFM + tid];
    __syncthreads();
    int o = wl[fm];
    int h = tid >> 2, w0 = (tid & 3) * 14;
    unsigned long long accp[7] = {0, 0, 0, 0, 0, 0, 0};
    for (int ii = 0; ii < 32; ii++) {
        __syncthreads();
        const float4* srcp = (const float4*)&g_Pad[b][ii][0];
        float4* dstp = (float4*)sIn;
        for (int p4 = tid; p4 < 900; p4 += 224) dstp[p4] = srcp[p4];
        if (tid < 25) sW[tid] = g_W2[(o * NC + wl[ii]) * 25 + tid];
        __syncthreads();
        #pragma unroll
        for (int kx = 0; kx < 5; kx++) {
            const float* rp = sIn + (h + kx) * 60 + w0;
            float rb[18];
            #pragma unroll
            for (int t = 0; t < 18; t++) rb[t] = rp[t];
            unsigned long long rbe[9], rbo[8];
            #pragma unroll
            for (int t = 0; t < 9; t++) rbe[t] = pack2(rb[2 * t], rb[2 * t + 1]);
            #pragma unroll
            for (int t = 0; t < 8; t++) rbo[t] = pack2(rb[2 * t + 1], rb[2 * t + 2]);
            #pragma unroll
            for (int ky = 0; ky < 5; ky++) {
                unsigned long long wv2 = bcast2(sW[kx * 5 + ky]);
                int m = ky >> 1;
                if ((ky & 1) == 0) {
                    #pragma unroll
                    for (int qq = 0; qq < 7; qq++) ffma2(accp[qq], rbe[qq + m], wv2);
                } else {
                    #pragma unroll
                    for (int qq = 0; qq < 7; qq++) ffma2(accp[qq], rbo[qq + m], wv2);
                }
            }
        }
    }
    const float* abo = g_Ab + (b * NC + o) * HW;
    float* op = out + (b * NFM + fm) * HW;
    #pragma unroll
    for (int qq = 0; qq < 7; qq++) {
        float a0, a1;
        unpack2(accp[qq], a0, a1);
        int p = h * WW + w0 + 2 * qq;
        op[p]     = abo[p]     + 0.1f * a0 * (1.0f / 32.0f);
        op[p + 1] = abo[p + 1] + 0.1f * a1 * (1.0f / 32.0f);
    }
}

extern "C" void kernel_launch(void* const* d_in, const int* in_sizes, int n_in,
                              void* d_out, int out_size) {
    const float* A     = (const float*)d_in[0];
    const float* K     = (const float*)d_in[1];
    const float* noise = (const float*)d_in[2];
    float* out = (float*)d_out;

    cudaFuncSetAttribute(k_kchange, cudaFuncAttributeMaxDynamicSharedMemorySize, KCH_SMEM);

    k_zero<<<400, 1024>>>();
    k_ab<<<2048, 256>>>(A, noise);
    k_winners<<<1, 512>>>();
    k_pad<<<dim3(16, 32), 256>>>();
    k_kchange<<<dim3(8, 16, 8), 320, KCH_SMEM>>>();
    k_combine<<<64, 256>>>(K);
    k_l2out<<<dim3(32, 16), 224>>>(out);
}

// round 8
// speedup vs baseline: 3.4506x; 1.8849x over previous
#include <cuda_runtime.h>

#define HH 56
#define WW 56
#define HW 3136
#define NB 16
#define NFM 32
#define NC 128

// ---------------- device scratch ----------------
__device__ float g_Ab[NB * NC * HW];
__device__ float g_sum[NB * NC];
__device__ int   g_fmidx[NB * NFM];
__device__ float g_Kch[NC * NC * 25];
__device__ float g_W2[NC * NC * 25];
__device__ float g_Pad[NB][NFM][3600];   // padded (60x60) winner channels

__device__ __forceinline__ int map2i(int i) { return i < 2 ? 3 - i : (i >= 54 ? 107 - i : i); }
__device__ __forceinline__ int mPad(int i)  { return i < 4 ? 5 - i : (i < 56 ? i - 2 : 109 - i); }

__device__ __forceinline__ void cp8(unsigned dst, const float* src) {
    asm volatile("cp.async.ca.shared.global [%0], [%1], 8;" ::
                 "r"(dst), "l"(__cvta_generic_to_global(src)));
}
__device__ __forceinline__ void cp_commit() { asm volatile("cp.async.commit_group;"); }

__device__ __forceinline__ unsigned long long bcast2(float v) {
    unsigned long long r;
    asm("mov.b64 %0, {%1, %1};" : "=l"(r) : "f"(v));
    return r;
}
__device__ __forceinline__ unsigned long long pack2(float lo, float hi) {
    unsigned long long r;
    asm("mov.b64 %0, {%1, %2};" : "=l"(r) : "f"(lo), "f"(hi));
    return r;
}
__device__ __forceinline__ void ffma2(unsigned long long& d, unsigned long long a,
                                      unsigned long long b) {
    asm("fma.rn.f32x2 %0, %1, %2, %0;" : "+l"(d) : "l"(a), "l"(b));
}
__device__ __forceinline__ void unpack2(unsigned long long v, float& lo, float& hi) {
    asm("mov.b64 {%0, %1}, %2;" : "=f"(lo), "=f"(hi) : "l"(v));
}

__device__ __forceinline__ void mma_tf32(float* d, unsigned a0, unsigned a1, unsigned a2,
                                         unsigned a3, unsigned b0, unsigned b1) {
    asm volatile("mma.sync.aligned.m16n8k8.row.col.f32.tf32.tf32.f32 "
                 "{%0,%1,%2,%3}, {%4,%5,%6,%7}, {%8,%9}, {%0,%1,%2,%3};"
                 : "+f"(d[0]), "+f"(d[1]), "+f"(d[2]), "+f"(d[3])
                 : "r"(a0), "r"(a1), "r"(a2), "r"(a3), "r"(b0), "r"(b1));
}

// ---------------- kernel 0: zero K_change ----------------
__global__ void k_zero() { g_Kch[blockIdx.x * 1024 + threadIdx.x] = 0.0f; }

// ---------------- kernel 1: Ab + per-map sums ----------------
__global__ __launch_bounds__(256) void k_ab(const float* __restrict__ A,
                                            const float* __restrict__ noise) {
    int bc = blockIdx.x;
    int b = bc >> 7, c = bc & 127, fm = c & 31;
    const float* aB = A + (b * NFM + fm) * HW;
    const float* nB = noise + bc * HW;
    float* oB = g_Ab + bc * HW;
    float s = 0.0f;
    for (int p = threadIdx.x; p < HW; p += 256) {
        int h = (p * 37450) >> 21;          // p / 56
        int w = p - h * WW;
        float v = aB[map2i(h) * WW + map2i(w)] + 0.1f * nB[p];
        v = fmaxf(v, 0.0f);
        oB[p] = v;
        s += v;
    }
    #pragma unroll
    for (int o = 16; o; o >>= 1) s += __shfl_xor_sync(0xffffffffu, s, o);
    __shared__ float red[8];
    if ((threadIdx.x & 31) == 0) red[threadIdx.x >> 5] = s;
    __syncthreads();
    if (threadIdx.x == 0) {
        float t = 0.0f;
        #pragma unroll
        for (int i = 0; i < 8; i++) t += red[i];
        g_sum[bc] = t;
    }
}

// ---------------- kernel 2: winners ----------------
__global__ void k_winners() {
    int t = threadIdx.x;
    if (t >= NB * NFM) return;
    int b = t >> 5, fm = t & 31;
    const float* s = g_sum + b * NC;
    float best = s[fm];
    int wi = 0;
    #pragma unroll
    for (int r = 1; r < 4; r++) {
        float v = s[r * NFM + fm];
        if (v > best) { best = v; wi = r; }
    }
    g_fmidx[t] = wi * NFM + fm;
}

// ---------------- kernel 2b: padded winner channels for l2out ----------------
__global__ __launch_bounds__(256) void k_pad() {
    int b = blockIdx.x, j = blockIdx.y;
    int c = g_fmidx[b * NFM + j];
    const float* src = g_Ab + (size_t)(b * NC + c) * HW;
    float* dst = &g_Pad[b][j][0];
    for (int p = threadIdx.x; p < 3600; p += 256) {
        int r = p / 60, s = p - r * 60;
        dst[p] = src[mPad(r) * WW + mPad(s)];
    }
}

// ---------------- kernel 3: K_change via tf32 mma.sync ----------------
// Kch[c, a, xy] = sum_p Am[c,p] * AbPad[a, shifted(p, xy)]
// Block = (atile of 8 a, b). 8 warps; warp = one a. M=32 winners, N=32 (25 valid xy),
// K = 3136 in 14 chunks of 4 image rows (28 k-steps of 8), cp.async double-buffered.
#define AM_STRIDE 230                         // 224 data + pad (conflict spread)
#define AM_FLTS  (32 * AM_STRIDE)             // 7360
#define AB_STRIDE 480                         // 8 rows x 60 per a
#define AB_FLTS  (8 * AB_STRIDE)              // 3840
#define KC_SMEM  ((2 * AM_FLTS + 2 * AB_FLTS) * 4)   // 89600 B

__device__ __forceinline__ void kc_load_chunk(float* smA, float* smB, const float* abB,
                                              const int* sWin, int aBase, int cc, int tid) {
    unsigned dA = (unsigned)__cvta_generic_to_shared(smA);
    #pragma unroll
    for (int t = 0; t < 14; t++) {            // 3584 cp8: Am 32j x 4rows x 56
        int idx = tid + t * 256;
        int j = idx / 112;
        int rem = idx - j * 112;
        int r = rem / 28, w = (rem - r * 28) * 2;
        cp8(dA + (unsigned)((j * AM_STRIDE + r * 56 + w) * 4),
            abB + (size_t)sWin[j] * HW + (cc * 4 + r) * WW + w);
    }
    unsigned dB = (unsigned)__cvta_generic_to_shared(smB);
    #pragma unroll
    for (int t = 0; t < 7; t++) {             // 1792 cp8: Ab 8a x 8 abpad rows x 56
        int idx = tid + t * 256;
        int a = idx / 224;
        int rem = idx - a * 224;
        int rr = rem / 28, w = (rem - rr * 28) * 2;
        int g = cc * 4 + rr;                  // abpad row; image row g-2
        unsigned off = (unsigned)((a * AB_STRIDE + rr * 60 + 2 + w) * 4);
        if (g >= 2 && g <= 57) {
            cp8(dB + off, abB + (size_t)(aBase + a) * HW + (g - 2) * WW + w);
        } else {
            *(float2*)(smB + a * AB_STRIDE + rr * 60 + 2 + w) = make_float2(0.f, 0.f);
        }
    }
}

__global__ __launch_bounds__(256, 2) void k_kchange() {
    extern __shared__ __align__(16) float dyn[];
    float* smA = dyn;                         // [2][AM_FLTS]
    float* smB = dyn + 2 * AM_FLTS;           // [2][AB_FLTS]
    __shared__ int sWin[32];
    int atile = blockIdx.x, b = blockIdx.y;
    int tid = threadIdx.x, wid = tid >> 5, lane = tid & 31;
    int gid = lane >> 2, tig = lane & 3;
    if (tid < 32) sWin[tid] = g_fmidx[b * NFM + tid];
    for (int p = tid; p < 2 * AM_FLTS + 2 * AB_FLTS; p += 256) dyn[p] = 0.f;
    __syncthreads();
    const float* abB = g_Ab + (size_t)(b * NC) * HW;
    int aBase = atile * 8;
    // per-thread B column constants: n = gid within each n-tile jt
    int cbs[4];
    #pragma unroll
    for (int jt = 0; jt < 4; jt++) {
        int xy = jt * 8 + gid; if (xy > 24) xy = 24;   // padding columns (not stored)
        int x = xy / 5, y = xy - x * 5;
        cbs[jt] = (4 - x) * 60 + (4 - y);
    }
    float d[2][4][4];
    #pragma unroll
    for (int m = 0; m < 2; m++)
        #pragma unroll
        for (int jt = 0; jt < 4; jt++)
            #pragma unroll
            for (int q = 0; q < 4; q++) d[m][jt][q] = 0.f;

    kc_load_chunk(smA, smB, abB, sWin, aBase, 0, tid);
    cp_commit();
    int aOff0 = gid * AM_STRIDE + tig;
    for (int cc = 0; cc < 14; cc++) {
        int st = cc & 1;
        if (cc + 1 < 14) {
            kc_load_chunk(smA + (st ^ 1) * AM_FLTS, smB + (st ^ 1) * AB_FLTS,
                          abB, sWin, aBase, cc + 1, tid);
            cp_commit();
            asm volatile("cp.async.wait_group 1;" ::: "memory");
        } else {
            asm volatile("cp.async.wait_group 0;" ::: "memory");
        }
        __syncthreads();
        const float* Ax = smA + st * AM_FLTS;
        const float* Bx = smB + st * AB_FLTS + wid * AB_STRIDE;
        #pragma unroll
        for (int rl = 0; rl < 4; rl++) {
            #pragma unroll
            for (int ws = 0; ws < 7; ws++) {
                int ao = aOff0 + rl * 56 + ws * 8;
                int bo = rl * 60 + ws * 8 + tig;
                unsigned a0 = __float_as_uint(Ax[ao]);
                unsigned a1 = __float_as_uint(Ax[ao + 8 * AM_STRIDE]);
                unsigned a2 = __float_as_uint(Ax[ao + 4]);
                unsigned a3 = __float_as_uint(Ax[ao + 8 * AM_STRIDE + 4]);
                unsigned a4 = __float_as_uint(Ax[ao + 16 * AM_STRIDE]);
                unsigned a5 = __float_as_uint(Ax[ao + 24 * AM_STRIDE]);
                unsigned a6 = __float_as_uint(Ax[ao + 16 * AM_STRIDE + 4]);
                unsigned a7 = __float_as_uint(Ax[ao + 24 * AM_STRIDE + 4]);
                #pragma unroll
                for (int jt = 0; jt < 4; jt++) {
                    unsigned b0 = __float_as_uint(Bx[cbs[jt] + bo]);
                    unsigned b1 = __float_as_uint(Bx[cbs[jt] + bo + 4]);
                    mma_tf32(d[0][jt], a0, a1, a2, a3, b0, b1);
                    mma_tf32(d[1][jt], a4, a5, a6, a7, b0, b1);
                }
            }
        }
        __syncthreads();
    }
    // store: thread holds D rows (gid, gid+8) cols (tig*2, tig*2+1) per (mtile, jt)
    int aCh = aBase + wid;
    #pragma unroll
    for (int m = 0; m < 2; m++) {
        int c0 = sWin[m * 16 + gid];
        int c1 = sWin[m * 16 + gid + 8];
        #pragma unroll
        for (int jt = 0; jt < 4; jt++) {
            int xy0 = jt * 8 + tig * 2;
            if (xy0 < 25) {
                atomicAdd(g_Kch + c0 * 3200 + aCh * 25 + xy0, d[m][jt][0]);
                atomicAdd(g_Kch + c1 * 3200 + aCh * 25 + xy0, d[m][jt][2]);
            }
            if (xy0 + 1 < 25) {
                atomicAdd(g_Kch + c0 * 3200 + aCh * 25 + xy0 + 1, d[m][jt][1]);
                atomicAdd(g_Kch + c1 * 3200 + aCh * 25 + xy0 + 1, d[m][jt][3]);
            }
        }
    }
}

// ---------------- kernel 4: combine weights ----------------
__global__ __launch_bounds__(256) void k_combine(const float* __restrict__ K) {
    int t = blockIdx.x * 256 + threadIdx.x;
    int o = t >> 7, i = t & 127;
    const float* kc = g_Kch + (i * NC + o) * 25;
    const float* kk = K + (o * NC + i) * 25;
    float v[25];
    float mn = 1e30f, mx = -1e30f;
    #pragma unroll
    for (int s = 0; s < 25; s++) {
        v[s] = kc[s] * (1.0f / 2048.0f);
        mn = fminf(mn, v[s]); mx = fmaxf(mx, v[s]);
    }
    float inv = 1.0f / (mx - mn + 1e-10f);
    float mn2 = 1e30f, mx2 = -1e30f;
    #pragma unroll
    for (int s = 0; s < 25; s++) {
        v[s] = 0.9f * kk[s] + 0.1f * ((v[s] - mn) * inv);
        mn2 = fminf(mn2, v[s]); mx2 = fmaxf(mx2, v[s]);
    }
    float inv2 = 1.0f / (mx2 - mn2 + 1e-10f);
    float* dst = g_W2 + (o * NC + i) * 25;
    #pragma unroll
    for (int s = 0; s < 25; s++) dst[s] = (v[s] - mn2) * inv2;
}

// ---------------- kernel 5: L2 conv + output (f32x2, streamed refill) ----------------
__global__ __launch_bounds__(224) void k_l2out(float* __restrict__ out) {
    __shared__ float sIn[3600];
    __shared__ float sW[25];
    __shared__ int wl[32];
    int b = blockIdx.y, fm = blockIdx.x, tid = threadIdx.x;
    if (tid < 32) wl[tid] = g_fmidx[b * NFM + tid];
    __syncthreads();
    int o = wl[fm];
    int h = tid >> 2, w0 = (tid & 3) * 14;
    unsigned long long accp[7] = {0, 0, 0, 0, 0, 0, 0};
    for (int ii = 0; ii < 32; ii++) {
        __syncthreads();
        const float4* srcp = (const float4*)&g_Pad[b][ii][0];
        float4* dstp = (float4*)sIn;
        for (int p4 = tid; p4 < 900; p4 += 224) dstp[p4] = srcp[p4];
        if (tid < 25) sW[tid] = g_W2[(o * NC + wl[ii]) * 25 + tid];
        __syncthreads();
        #pragma unroll
        for (int kx = 0; kx < 5; kx++) {
            const float* rp = sIn + (h + kx) * 60 + w0;
            float rb[18];
            #pragma unroll
            for (int t = 0; t < 18; t++) rb[t] = rp[t];
            unsigned long long rbe[9], rbo[8];
            #pragma unroll
            for (int t = 0; t < 9; t++) rbe[t] = pack2(rb[2 * t], rb[2 * t + 1]);
            #pragma unroll
            for (int t = 0; t < 8; t++) rbo[t] = pack2(rb[2 * t + 1], rb[2 * t + 2]);
            #pragma unroll
            for (int ky = 0; ky < 5; ky++) {
                unsigned long long wv2 = bcast2(sW[kx * 5 + ky]);
                int m = ky >> 1;
                if ((ky & 1) == 0) {
                    #pragma unroll
                    for (int qq = 0; qq < 7; qq++) ffma2(accp[qq], rbe[qq + m], wv2);
                } else {
                    #pragma unroll
                    for (int qq = 0; qq < 7; qq++) ffma2(accp[qq], rbo[qq + m], wv2);
                }
            }
        }
    }
    const float* abo = g_Ab + (b * NC + o) * HW;
    float* op = out + (b * NFM + fm) * HW;
    #pragma unroll
    for (int qq = 0; qq < 7; qq++) {
        float a0, a1;
        unpack2(accp[qq], a0, a1);
        int p = h * WW + w0 + 2 * qq;
        op[p]     = abo[p]     + 0.1f * a0 * (1.0f / 32.0f);
        op[p + 1] = abo[p + 1] + 0.1f * a1 * (1.0f / 32.0f);
    }
}

extern "C" void kernel_launch(void* const* d_in, const int* in_sizes, int n_in,
                              void* d_out, int out_size) {
    const float* A     = (const float*)d_in[0];
    const float* K     = (const float*)d_in[1];
    const float* noise = (const float*)d_in[2];
    float* out = (float*)d_out;

    cudaFuncSetAttribute(k_kchange, cudaFuncAttributeMaxDynamicSharedMemorySize, KC_SMEM);

    k_zero<<<400, 1024>>>();
    k_ab<<<2048, 256>>>(A, noise);
    k_winners<<<1, 512>>>();
    k_pad<<<dim3(16, 32), 256>>>();
    k_kchange<<<dim3(16, 16), 256, KC_SMEM>>>();
    k_combine<<<64, 256>>>(K);
    k_l2out<<<dim3(32, 16), 224>>>(out);
}

// round 9
// speedup vs baseline: 4.4588x; 1.2922x over previous
#include <cuda_runtime.h>

#define HH 56
#define WW 56
#define HW 3136
#define NB 16
#define NFM 32
#define NC 128

// ---------------- device scratch ----------------
__device__ float g_Ab[NB * NC * HW];
__device__ float g_sum[NB * NC];
__device__ int   g_fmidx[NB * NFM];
__device__ float g_Kch[NC * NC * 25];
__device__ float g_W2[NC * NC * 25];
__device__ float g_Pad[NB][NFM][3600];   // padded (60x60) winner channels

__device__ __forceinline__ int map2i(int i) { return i < 2 ? 3 - i : (i >= 54 ? 107 - i : i); }
__device__ __forceinline__ int mPad(int i)  { return i < 4 ? 5 - i : (i < 56 ? i - 2 : 109 - i); }

__device__ __forceinline__ void cp4(unsigned dst, const float* src) {
    asm volatile("cp.async.ca.shared.global [%0], [%1], 4;" ::
                 "r"(dst), "l"(__cvta_generic_to_global(src)));
}
__device__ __forceinline__ void cp8(unsigned dst, const float* src) {
    asm volatile("cp.async.ca.shared.global [%0], [%1], 8;" ::
                 "r"(dst), "l"(__cvta_generic_to_global(src)));
}
__device__ __forceinline__ void cp16(unsigned dst, const float* src) {
    asm volatile("cp.async.cg.shared.global [%0], [%1], 16;" ::
                 "r"(dst), "l"(__cvta_generic_to_global(src)));
}
__device__ __forceinline__ void cp_commit() { asm volatile("cp.async.commit_group;"); }

__device__ __forceinline__ void mma_tf32(float* d, unsigned a0, unsigned a1, unsigned a2,
                                         unsigned a3, unsigned b0, unsigned b1) {
    asm volatile("mma.sync.aligned.m16n8k8.row.col.f32.tf32.tf32.f32 "
                 "{%0,%1,%2,%3}, {%4,%5,%6,%7}, {%8,%9}, {%0,%1,%2,%3};"
                 : "+f"(d[0]), "+f"(d[1]), "+f"(d[2]), "+f"(d[3])
                 : "r"(a0), "r"(a1), "r"(a2), "r"(a3), "r"(b0), "r"(b1));
}

// ---------------- kernel 0: zero K_change ----------------
__global__ void k_zero() { g_Kch[blockIdx.x * 1024 + threadIdx.x] = 0.0f; }

// ---------------- kernel 1: Ab + per-map sums ----------------
__global__ __launch_bounds__(256) void k_ab(const float* __restrict__ A,
                                            const float* __restrict__ noise) {
    int bc = blockIdx.x;
    int b = bc >> 7, c = bc & 127, fm = c & 31;
    const float* aB = A + (b * NFM + fm) * HW;
    const float* nB = noise + bc * HW;
    float* oB = g_Ab + bc * HW;
    float s = 0.0f;
    for (int p = threadIdx.x; p < HW; p += 256) {
        int h = (p * 37450) >> 21;          // p / 56
        int w = p - h * WW;
        float v = aB[map2i(h) * WW + map2i(w)] + 0.1f * nB[p];
        v = fmaxf(v, 0.0f);
        oB[p] = v;
        s += v;
    }
    #pragma unroll
    for (int o = 16; o; o >>= 1) s += __shfl_xor_sync(0xffffffffu, s, o);
    __shared__ float red[8];
    if ((threadIdx.x & 31) == 0) red[threadIdx.x >> 5] = s;
    __syncthreads();
    if (threadIdx.x == 0) {
        float t = 0.0f;
        #pragma unroll
        for (int i = 0; i < 8; i++) t += red[i];
        g_sum[bc] = t;
    }
}

// ---------------- kernel 2: winners ----------------
__global__ void k_winners() {
    int t = threadIdx.x;
    if (t >= NB * NFM) return;
    int b = t >> 5, fm = t & 31;
    const float* s = g_sum + b * NC;
    float best = s[fm];
    int wi = 0;
    #pragma unroll
    for (int r = 1; r < 4; r++) {
        float v = s[r * NFM + fm];
        if (v > best) { best = v; wi = r; }
    }
    g_fmidx[t] = wi * NFM + fm;
}

// ---------------- kernel 2b: padded winner channels ----------------
__global__ __launch_bounds__(256) void k_pad() {
    int b = blockIdx.x, j = blockIdx.y;
    int c = g_fmidx[b * NFM + j];
    const float* src = g_Ab + (size_t)(b * NC + c) * HW;
    float* dst = &g_Pad[b][j][0];
    for (int p = threadIdx.x; p < 3600; p += 256) {
        int r = p / 60, s = p - r * 60;
        dst[p] = src[mPad(r) * WW + mPad(s)];
    }
}

// ---------------- kernel 3: K_change via tf32 mma.sync ----------------
#define AM_STRIDE 230
#define AM_FLTS  (32 * AM_STRIDE)
#define AB_STRIDE 480
#define AB_FLTS  (8 * AB_STRIDE)
#define KC_SMEM  ((2 * AM_FLTS + 2 * AB_FLTS) * 4)

__device__ __forceinline__ void kc_load_chunk(float* smA, float* smB, const float* abB,
                                              const int* sWin, int aBase, int cc, int tid) {
    unsigned dA = (unsigned)__cvta_generic_to_shared(smA);
    #pragma unroll
    for (int t = 0; t < 14; t++) {
        int idx = tid + t * 256;
        int j = idx / 112;
        int rem = idx - j * 112;
        int r = rem / 28, w = (rem - r * 28) * 2;
        cp8(dA + (unsigned)((j * AM_STRIDE + r * 56 + w) * 4),
            abB + (size_t)sWin[j] * HW + (cc * 4 + r) * WW + w);
    }
    unsigned dB = (unsigned)__cvta_generic_to_shared(smB);
    #pragma unroll
    for (int t = 0; t < 7; t++) {
        int idx = tid + t * 256;
        int a = idx / 224;
        int rem = idx - a * 224;
        int rr = rem / 28, w = (rem - rr * 28) * 2;
        int g = cc * 4 + rr;
        unsigned off = (unsigned)((a * AB_STRIDE + rr * 60 + 2 + w) * 4);
        if (g >= 2 && g <= 57) {
            cp8(dB + off, abB + (size_t)(aBase + a) * HW + (g - 2) * WW + w);
        } else {
            *(float2*)(smB + a * AB_STRIDE + rr * 60 + 2 + w) = make_float2(0.f, 0.f);
        }
    }
}

__global__ __launch_bounds__(256, 2) void k_kchange() {
    extern __shared__ __align__(16) float dyn[];
    float* smA = dyn;
    float* smB = dyn + 2 * AM_FLTS;
    __shared__ int sWin[32];
    int atile = blockIdx.x, b = blockIdx.y;
    int tid = threadIdx.x, wid = tid >> 5, lane = tid & 31;
    int gid = lane >> 2, tig = lane & 3;
    if (tid < 32) sWin[tid] = g_fmidx[b * NFM + tid];
    for (int p = tid; p < 2 * AM_FLTS + 2 * AB_FLTS; p += 256) dyn[p] = 0.f;
    __syncthreads();
    const float* abB = g_Ab + (size_t)(b * NC) * HW;
    int aBase = atile * 8;
    int cbs[4];
    #pragma unroll
    for (int jt = 0; jt < 4; jt++) {
        int xy = jt * 8 + gid; if (xy > 24) xy = 24;
        int x = xy / 5, y = xy - x * 5;
        cbs[jt] = (4 - x) * 60 + (4 - y);
    }
    float d[2][4][4];
    #pragma unroll
    for (int m = 0; m < 2; m++)
        #pragma unroll
        for (int jt = 0; jt < 4; jt++)
            #pragma unroll
            for (int q = 0; q < 4; q++) d[m][jt][q] = 0.f;

    kc_load_chunk(smA, smB, abB, sWin, aBase, 0, tid);
    cp_commit();
    int aOff0 = gid * AM_STRIDE + tig;
    for (int cc = 0; cc < 14; cc++) {
        int st = cc & 1;
        if (cc + 1 < 14) {
            kc_load_chunk(smA + (st ^ 1) * AM_FLTS, smB + (st ^ 1) * AB_FLTS,
                          abB, sWin, aBase, cc + 1, tid);
            cp_commit();
            asm volatile("cp.async.wait_group 1;" ::: "memory");
        } else {
            asm volatile("cp.async.wait_group 0;" ::: "memory");
        }
        __syncthreads();
        const float* Ax = smA + st * AM_FLTS;
        const float* Bx = smB + st * AB_FLTS + wid * AB_STRIDE;
        #pragma unroll
        for (int rl = 0; rl < 4; rl++) {
            #pragma unroll
            for (int ws = 0; ws < 7; ws++) {
                int ao = aOff0 + rl * 56 + ws * 8;
                int bo = rl * 60 + ws * 8 + tig;
                unsigned a0 = __float_as_uint(Ax[ao]);
                unsigned a1 = __float_as_uint(Ax[ao + 8 * AM_STRIDE]);
                unsigned a2 = __float_as_uint(Ax[ao + 4]);
                unsigned a3 = __float_as_uint(Ax[ao + 8 * AM_STRIDE + 4]);
                unsigned a4 = __float_as_uint(Ax[ao + 16 * AM_STRIDE]);
                unsigned a5 = __float_as_uint(Ax[ao + 24 * AM_STRIDE]);
                unsigned a6 = __float_as_uint(Ax[ao + 16 * AM_STRIDE + 4]);
                unsigned a7 = __float_as_uint(Ax[ao + 24 * AM_STRIDE + 4]);
                #pragma unroll
                for (int jt = 0; jt < 4; jt++) {
                    unsigned b0 = __float_as_uint(Bx[cbs[jt] + bo]);
                    unsigned b1 = __float_as_uint(Bx[cbs[jt] + bo + 4]);
                    mma_tf32(d[0][jt], a0, a1, a2, a3, b0, b1);
                    mma_tf32(d[1][jt], a4, a5, a6, a7, b0, b1);
                }
            }
        }
        __syncthreads();
    }
    int aCh = aBase + wid;
    #pragma unroll
    for (int m = 0; m < 2; m++) {
        int c0 = sWin[m * 16 + gid];
        int c1 = sWin[m * 16 + gid + 8];
        #pragma unroll
        for (int jt = 0; jt < 4; jt++) {
            int xy0 = jt * 8 + tig * 2;
            if (xy0 < 25) {
                atomicAdd(g_Kch + c0 * 3200 + aCh * 25 + xy0, d[m][jt][0]);
                atomicAdd(g_Kch + c1 * 3200 + aCh * 25 + xy0, d[m][jt][2]);
            }
            if (xy0 + 1 < 25) {
                atomicAdd(g_Kch + c0 * 3200 + aCh * 25 + xy0 + 1, d[m][jt][1]);
                atomicAdd(g_Kch + c1 * 3200 + aCh * 25 + xy0 + 1, d[m][jt][3]);
            }
        }
    }
}

// ---------------- kernel 4: combine weights ----------------
__global__ __launch_bounds__(256) void k_combine(const float* __restrict__ K) {
    int t = blockIdx.x * 256 + threadIdx.x;
    int o = t >> 7, i = t & 127;
    const float* kc = g_Kch + (i * NC + o) * 25;
    const float* kk = K + (o * NC + i) * 25;
    float v[25];
    float mn = 1e30f, mx = -1e30f;
    #pragma unroll
    for (int s = 0; s < 25; s++) {
        v[s] = kc[s] * (1.0f / 2048.0f);
        mn = fminf(mn, v[s]); mx = fmaxf(mx, v[s]);
    }
    float inv = 1.0f / (mx - mn + 1e-10f);
    float mn2 = 1e30f, mx2 = -1e30f;
    #pragma unroll
    for (int s = 0; s < 25; s++) {
        v[s] = 0.9f * kk[s] + 0.1f * ((v[s] - mn) * inv);
        mn2 = fminf(mn2, v[s]); mx2 = fmaxf(mx2, v[s]);
    }
    float inv2 = 1.0f / (mx2 - mn2 + 1e-10f);
    float* dst = g_W2 + (o * NC + i) * 25;
    #pragma unroll
    for (int s = 0; s < 25; s++) dst[s] = (v[s] - mn2) * inv2;
}

// ---------------- kernel 5: L2 conv + output via tf32 mma ----------------
// Per (chunk q of 7 image rows, batch b): D[fm, p] = sum_{i,xy} W2[o_fm, wl_i, xy] * PadT[i, p+off(xy)]
// M=32 fm (2 m-tiles), K per i = 32 (25 valid xy, 4 k-steps), N=392 px (49 n-tiles, 13/warp).
#define A_STR 36
__global__ __launch_bounds__(128, 2) void k_l2mma(float* __restrict__ out) {
    __shared__ float sA[2][32 * A_STR];     // W2 slice, cols 25..31 zero
    __shared__ __align__(16) float sP[2][672];  // 11 rows x 60 pad strip
    __shared__ int wl[32];
    int q = blockIdx.x, b = blockIdx.y;
    int tid = threadIdx.x, wid = tid >> 5, lane = tid & 31;
    int gid = lane >> 2, tig = lane & 3;
    if (tid < 32) wl[tid] = g_fmidx[b * NFM + tid];
    for (int p = tid; p < 2 * 32 * A_STR; p += 128) ((float*)sA)[p] = 0.f;
    __syncthreads();

    // per-thread B k-row offsets (clamped; A zero-cols kill invalid xy)
    int offk[4][2];
    #pragma unroll
    for (int ks = 0; ks < 4; ks++) {
        #pragma unroll
        for (int hh = 0; hh < 2; hh++) {
            int xy = ks * 8 + tig + hh * 4; if (xy > 24) xy = 24;
            int kx = xy / 5, ky = xy - kx * 5;
            offk[ks][hh] = kx * 60 + ky;
        }
    }
    // n-tile geometry for this warp (13 tiles, warp3 has 10 valid)
    int ntBeg = wid * 13;
    float acc[13][2][4];
    #pragma unroll
    for (int j = 0; j < 13; j++)
        #pragma unroll
        for (int m = 0; m < 2; m++)
            #pragma unroll
            for (int v = 0; v < 4; v++) acc[j][m][v] = 0.f;

    // ---- preload i = 0 ----
    {
        int iCh = wl[0];
        unsigned dA = (unsigned)__cvta_generic_to_shared(&sA[0][0]);
        for (int idx = tid; idx < 800; idx += 128) {
            int m = idx / 25, k = idx - m * 25;
            cp4(dA + (unsigned)((m * A_STR + k) * 4),
                g_W2 + ((size_t)wl[m] * NC + iCh) * 25 + k);
        }
        unsigned dP = (unsigned)__cvta_generic_to_shared(&sP[0][0]);
        const float* src = &g_Pad[b][0][0] + q * 420;
        for (int idx = tid; idx < 165; idx += 128)
            cp16(dP + (unsigned)(idx * 16), src + idx * 4);
        cp_commit();
    }
    for (int i = 0; i < 32; i++) {
        int st = i & 1;
        if (i + 1 < 32) {
            int iCh = wl[i + 1];
            unsigned dA = (unsigned)__cvta_generic_to_shared(&sA[st ^ 1][0]);
            for (int idx = tid; idx < 800; idx += 128) {
                int m = idx / 25, k = idx - m * 25;
                cp4(dA + (unsigned)((m * A_STR + k) * 4),
                    g_W2 + ((size_t)wl[m] * NC + iCh) * 25 + k);
            }
            unsigned dP = (unsigned)__cvta_generic_to_shared(&sP[st ^ 1][0]);
            const float* src = &g_Pad[b][i + 1][0] + q * 420;
            for (int idx = tid; idx < 165; idx += 128)
                cp16(dP + (unsigned)(idx * 16), src + idx * 4);
            cp_commit();
            asm volatile("cp.async.wait_group 1;" ::: "memory");
        } else {
            asm volatile("cp.async.wait_group 0;" ::: "memory");
        }
        __syncthreads();
        const float* Ax = &sA[st][0];
        const float* Pz = &sP[st][0];
        // hoist A fragments
        unsigned aF[2][4][4];
        #pragma unroll
        for (int mt = 0; mt < 2; mt++)
            #pragma unroll
            for (int ks = 0; ks < 4; ks++) {
                int base = (mt * 16 + gid) * A_STR + ks * 8 + tig;
                aF[mt][ks][0] = __float_as_uint(Ax[base]);
                aF[mt][ks][1] = __float_as_uint(Ax[base + 8 * A_STR]);
                aF[mt][ks][2] = __float_as_uint(Ax[base + 4]);
                aF[mt][ks][3] = __float_as_uint(Ax[base + 8 * A_STR + 4]);
            }
        #pragma unroll
        for (int j = 0; j < 13; j++) {
            int nt = ntBeg + j;
            if (nt < 49) {
                int lp = nt * 8 + gid;
                int r = (lp * 1171) >> 16;        // lp / 56
                int base = r * 4 + lp;            // r*60 + (lp - r*56)
                #pragma unroll
                for (int ks = 0; ks < 4; ks++) {
                    unsigned b0 = __float_as_uint(Pz[base + offk[ks][0]]);
                    unsigned b1 = __float_as_uint(Pz[base + offk[ks][1]]);
                    mma_tf32(acc[j][0], aF[0][ks][0], aF[0][ks][1], aF[0][ks][2],
                             aF[0][ks][3], b0, b1);
                    mma_tf32(acc[j][1], aF[1][ks][0], aF[1][ks][1], aF[1][ks][2],
                             aF[1][ks][3], b0, b1);
                }
            }
        }
        __syncthreads();
    }
    // epilogue: O = Ab[gathered] + (0.1/32) * D
    const float cmul = 0.1f / 32.0f;
    #pragma unroll
    for (int j = 0; j < 13; j++) {
        int nt = ntBeg + j;
        if (nt < 49) {
            int p = q * 392 + nt * 8 + tig * 2;
            #pragma unroll
            for (int mt = 0; mt < 2; mt++) {
                int fm0 = mt * 16 + gid, fm1 = fm0 + 8;
                const float* ab0 = g_Ab + ((size_t)b * NC + wl[fm0]) * HW;
                const float* ab1 = g_Ab + ((size_t)b * NC + wl[fm1]) * HW;
                float* o0 = out + ((size_t)b * NFM + fm0) * HW;
                float* o1 = out + ((size_t)b * NFM + fm1) * HW;
                o0[p]     = ab0[p]     + cmul * acc[j][mt][0];
                o0[p + 1] = ab0[p + 1] + cmul * acc[j][mt][1];
                o1[p]     = ab1[p]     + cmul * acc[j][mt][2];
                o1[p + 1] = ab1[p + 1] + cmul * acc[j][mt][3];
            }
        }
    }
}

extern "C" void kernel_launch(void* const* d_in, const int* in_sizes, int n_in,
                              void* d_out, int out_size) {
    const float* A     = (const float*)d_in[0];
    const float* K     = (const float*)d_in[1];
    const float* noise = (const float*)d_in[2];
    float* out = (float*)d_out;

    cudaFuncSetAttribute(k_kchange, cudaFuncAttributeMaxDynamicSharedMemorySize, KC_SMEM);

    k_zero<<<400, 1024>>>();
    k_ab<<<2048, 256>>>(A, noise);
    k_winners<<<1, 512>>>();
    k_pad<<<dim3(16, 32), 256>>>();
    k_kchange<<<dim3(16, 16), 256, KC_SMEM>>>();
    k_combine<<<64, 256>>>(K);
    k_l2mma<<<dim3(8, 16), 128>>>(out);
}

// round 10
// speedup vs baseline: 4.6535x; 1.0437x over previous
#include <cuda_runtime.h>

#define HH 56
#define WW 56
#define HW 3136
#define NB 16
#define NFM 32
#define NC 128

// ---------------- device scratch ----------------
__device__ float g_Ab[NB * NC * HW];
__device__ float g_sum[NB * NC];
__device__ int   g_fmidx[NB * NFM];
__device__ float g_Kch[NC * NC * 25];
__device__ float g_W2[NC * NC * 25];
__device__ float g_Pad[NB][NFM][3600];   // padded (60x60) winner channels, tf32-rounded

__device__ __forceinline__ int map2i(int i) { return i < 2 ? 3 - i : (i >= 54 ? 107 - i : i); }
__device__ __forceinline__ int mPad(int i)  { return i < 4 ? 5 - i : (i < 56 ? i - 2 : 109 - i); }

__device__ __forceinline__ float tf32r(float x) {
    float r; asm("cvt.rna.tf32.f32 %0, %1;" : "=f"(r) : "f"(x)); return r;
}
__device__ __forceinline__ void cp4(unsigned dst, const float* src) {
    asm volatile("cp.async.ca.shared.global [%0], [%1], 4;" ::
                 "r"(dst), "l"(__cvta_generic_to_global(src)));
}
__device__ __forceinline__ void cp8(unsigned dst, const float* src) {
    asm volatile("cp.async.ca.shared.global [%0], [%1], 8;" ::
                 "r"(dst), "l"(__cvta_generic_to_global(src)));
}
__device__ __forceinline__ void cp16(unsigned dst, const float* src) {
    asm volatile("cp.async.cg.shared.global [%0], [%1], 16;" ::
                 "r"(dst), "l"(__cvta_generic_to_global(src)));
}
__device__ __forceinline__ void cp_commit() { asm volatile("cp.async.commit_group;"); }

__device__ __forceinline__ void mma_tf32(float* d, unsigned a0, unsigned a1, unsigned a2,
                                         unsigned a3, unsigned b0, unsigned b1) {
    asm volatile("mma.sync.aligned.m16n8k8.row.col.f32.tf32.tf32.f32 "
                 "{%0,%1,%2,%3}, {%4,%5,%6,%7}, {%8,%9}, {%0,%1,%2,%3};"
                 : "+f"(d[0]), "+f"(d[1]), "+f"(d[2]), "+f"(d[3])
                 : "r"(a0), "r"(a1), "r"(a2), "r"(a3), "r"(b0), "r"(b1));
}

// ---------------- kernel 0: zero K_change ----------------
__global__ void k_zero() { g_Kch[blockIdx.x * 1024 + threadIdx.x] = 0.0f; }

// ---------------- kernel 1: Ab + per-map sums (smem-staged A, float4 streams) ----------------
__global__ __launch_bounds__(256) void k_ab(const float* __restrict__ A,
                                            const float* __restrict__ noise) {
    __shared__ float sA[HW];
    __shared__ float red[8];
    int bf = blockIdx.x;             // b*32 + fm
    int b = bf >> 5, fm = bf & 31;
    const float4* a4 = (const float4*)(A + (size_t)(b * NFM + fm) * HW);
    for (int p = threadIdx.x; p < 784; p += 256) ((float4*)sA)[p] = a4[p];
    __syncthreads();
    for (int r = 0; r < 4; r++) {
        int c = r * NFM + fm;
        const float4* n4 = (const float4*)(noise + ((size_t)b * NC + c) * HW);
        float4* o4 = (float4*)(g_Ab + ((size_t)b * NC + c) * HW);
        float s = 0.0f;
        for (int p = threadIdx.x; p < 784; p += 256) {
            float4 nv = n4[p];
            int pix = p * 4;
            int h = (pix * 37450) >> 21;     // pix / 56
            int w = pix - h * WW;            // w <= 52, so w..w+3 same row
            int hm = map2i(h) * WW;
            float4 v;
            v.x = fmaxf(sA[hm + map2i(w)]     + 0.1f * nv.x, 0.0f);
            v.y = fmaxf(sA[hm + map2i(w + 1)] + 0.1f * nv.y, 0.0f);
            v.z = fmaxf(sA[hm + map2i(w + 2)] + 0.1f * nv.z, 0.0f);
            v.w = fmaxf(sA[hm + map2i(w + 3)] + 0.1f * nv.w, 0.0f);
            o4[p] = v;
            s += v.x + v.y + v.z + v.w;
        }
        #pragma unroll
        for (int o = 16; o; o >>= 1) s += __shfl_xor_sync(0xffffffffu, s, o);
        if ((threadIdx.x & 31) == 0) red[threadIdx.x >> 5] = s;
        __syncthreads();
        if (threadIdx.x == 0) {
            float t = 0.0f;
            #pragma unroll
            for (int i = 0; i < 8; i++) t += red[i];
            g_sum[b * NC + c] = t;
        }
        __syncthreads();
    }
}

// ---------------- kernel 2: winners ----------------
__global__ void k_winners() {
    int t = threadIdx.x;
    if (t >= NB * NFM) return;
    int b = t >> 5, fm = t & 31;
    const float* s = g_sum + b * NC;
    float best = s[fm];
    int wi = 0;
    #pragma unroll
    for (int r = 1; r < 4; r++) {
        float v = s[r * NFM + fm];
        if (v > best) { best = v; wi = r; }
    }
    g_fmidx[t] = wi * NFM + fm;
}

// ---------------- kernel 2b: padded winner channels (tf32-rounded) ----------------
__global__ __launch_bounds__(256) void k_pad() {
    int b = blockIdx.x, j = blockIdx.y;
    int c = g_fmidx[b * NFM + j];
    const float* src = g_Ab + (size_t)(b * NC + c) * HW;
    float* dst = &g_Pad[b][j][0];
    for (int p = threadIdx.x; p < 3600; p += 256) {
        int r = p / 60, s = p - r * 60;
        dst[p] = tf32r(src[mPad(r) * WW + mPad(s)]);
    }
}

// ---------------- kernel 3: K_change via tf32 mma.sync ----------------
#define AM_STRIDE 230
#define AM_FLTS  (32 * AM_STRIDE)
#define AB_STRIDE 480
#define AB_FLTS  (8 * AB_STRIDE)
#define KC_SMEM  ((2 * AM_FLTS + 2 * AB_FLTS) * 4)

__device__ __forceinline__ void kc_load_chunk(float* smA, float* smB, const float* abB,
                                              const int* sWin, int aBase, int cc, int tid) {
    unsigned dA = (unsigned)__cvta_generic_to_shared(smA);
    #pragma unroll
    for (int t = 0; t < 14; t++) {
        int idx = tid + t * 256;
        int j = idx / 112;
        int rem = idx - j * 112;
        int r = rem / 28, w = (rem - r * 28) * 2;
        cp8(dA + (unsigned)((j * AM_STRIDE + r * 56 + w) * 4),
            abB + (size_t)sWin[j] * HW + (cc * 4 + r) * WW + w);
    }
    unsigned dB = (unsigned)__cvta_generic_to_shared(smB);
    #pragma unroll
    for (int t = 0; t < 7; t++) {
        int idx = tid + t * 256;
        int a = idx / 224;
        int rem = idx - a * 224;
        int rr = rem / 28, w = (rem - rr * 28) * 2;
        int g = cc * 4 + rr;
        unsigned off = (unsigned)((a * AB_STRIDE + rr * 60 + 2 + w) * 4);
        if (g >= 2 && g <= 57) {
            cp8(dB + off, abB + (size_t)(aBase + a) * HW + (g - 2) * WW + w);
        } else {
            *(float2*)(smB + a * AB_STRIDE + rr * 60 + 2 + w) = make_float2(0.f, 0.f);
        }
    }
}

__global__ __launch_bounds__(256, 2) void k_kchange() {
    extern __shared__ __align__(16) float dyn[];
    float* smA = dyn;
    float* smB = dyn + 2 * AM_FLTS;
    __shared__ int sWin[32];
    int atile = blockIdx.x, b = blockIdx.y;
    int tid = threadIdx.x, wid = tid >> 5, lane = tid & 31;
    int gid = lane >> 2, tig = lane & 3;
    if (tid < 32) sWin[tid] = g_fmidx[b * NFM + tid];
    for (int p = tid; p < 2 * AM_FLTS + 2 * AB_FLTS; p += 256) dyn[p] = 0.f;
    __syncthreads();
    const float* abB = g_Ab + (size_t)(b * NC) * HW;
    int aBase = atile * 8;
    int cbs[4];
    #pragma unroll
    for (int jt = 0; jt < 4; jt++) {
        int xy = jt * 8 + gid; if (xy > 24) xy = 24;
        int x = xy / 5, y = xy - x * 5;
        cbs[jt] = (4 - x) * 60 + (4 - y);
    }
    float d[2][4][4];
    #pragma unroll
    for (int m = 0; m < 2; m++)
        #pragma unroll
        for (int jt = 0; jt < 4; jt++)
            #pragma unroll
            for (int q = 0; q < 4; q++) d[m][jt][q] = 0.f;

    kc_load_chunk(smA, smB, abB, sWin, aBase, 0, tid);
    cp_commit();
    int aOff0 = gid * AM_STRIDE + tig;
    for (int cc = 0; cc < 14; cc++) {
        int st = cc & 1;
        if (cc + 1 < 14) {
            kc_load_chunk(smA + (st ^ 1) * AM_FLTS, smB + (st ^ 1) * AB_FLTS,
                          abB, sWin, aBase, cc + 1, tid);
            cp_commit();
            asm volatile("cp.async.wait_group 1;" ::: "memory");
        } else {
            asm volatile("cp.async.wait_group 0;" ::: "memory");
        }
        __syncthreads();
        const float* Ax = smA + st * AM_FLTS;
        const float* Bx = smB + st * AB_FLTS + wid * AB_STRIDE;
        #pragma unroll
        for (int rl = 0; rl < 4; rl++) {
            #pragma unroll
            for (int ws = 0; ws < 7; ws++) {
                int ao = aOff0 + rl * 56 + ws * 8;
                int bo = rl * 60 + ws * 8 + tig;
                unsigned a0 = __float_as_uint(Ax[ao]);
                unsigned a1 = __float_as_uint(Ax[ao + 8 * AM_STRIDE]);
                unsigned a2 = __float_as_uint(Ax[ao + 4]);
                unsigned a3 = __float_as_uint(Ax[ao + 8 * AM_STRIDE + 4]);
                unsigned a4 = __float_as_uint(Ax[ao + 16 * AM_STRIDE]);
                unsigned a5 = __float_as_uint(Ax[ao + 24 * AM_STRIDE]);
                unsigned a6 = __float_as_uint(Ax[ao + 16 * AM_STRIDE + 4]);
                unsigned a7 = __float_as_uint(Ax[ao + 24 * AM_STRIDE + 4]);
                #pragma unroll
                for (int jt = 0; jt < 4; jt++) {
                    unsigned b0 = __float_as_uint(Bx[cbs[jt] + bo]);
                    unsigned b1 = __float_as_uint(Bx[cbs[jt] + bo + 4]);
                    mma_tf32(d[0][jt], a0, a1, a2, a3, b0, b1);
                    mma_tf32(d[1][jt], a4, a5, a6, a7, b0, b1);
                }
            }
        }
        __syncthreads();
    }
    int aCh = aBase + wid;
    #pragma unroll
    for (int m = 0; m < 2; m++) {
        int c0 = sWin[m * 16 + gid];
        int c1 = sWin[m * 16 + gid + 8];
        #pragma unroll
        for (int jt = 0; jt < 4; jt++) {
            int xy0 = jt * 8 + tig * 2;
            if (xy0 < 25) {
                atomicAdd(g_Kch + c0 * 3200 + aCh * 25 + xy0, d[m][jt][0]);
                atomicAdd(g_Kch + c1 * 3200 + aCh * 25 + xy0, d[m][jt][2]);
            }
            if (xy0 + 1 < 25) {
                atomicAdd(g_Kch + c0 * 3200 + aCh * 25 + xy0 + 1, d[m][jt][1]);
                atomicAdd(g_Kch + c1 * 3200 + aCh * 25 + xy0 + 1, d[m][jt][3]);
            }
        }
    }
}

// ---------------- kernel 4: combine weights (tf32-rounded output) ----------------
__global__ __launch_bounds__(256) void k_combine(const float* __restrict__ K) {
    int t = blockIdx.x * 256 + threadIdx.x;
    int o = t >> 7, i = t & 127;
    const float* kc = g_Kch + (i * NC + o) * 25;
    const float* kk = K + (o * NC + i) * 25;
    float v[25];
    float mn = 1e30f, mx = -1e30f;
    #pragma unroll
    for (int s = 0; s < 25; s++) {
        v[s] = kc[s] * (1.0f / 2048.0f);
        mn = fminf(mn, v[s]); mx = fmaxf(mx, v[s]);
    }
    float inv = 1.0f / (mx - mn + 1e-10f);
    float mn2 = 1e30f, mx2 = -1e30f;
    #pragma unroll
    for (int s = 0; s < 25; s++) {
        v[s] = 0.9f * kk[s] + 0.1f * ((v[s] - mn) * inv);
        mn2 = fminf(mn2, v[s]); mx2 = fmaxf(mx2, v[s]);
    }
    float inv2 = 1.0f / (mx2 - mn2 + 1e-10f);
    float* dst = g_W2 + (o * NC + i) * 25;
    #pragma unroll
    for (int s = 0; s < 25; s++) dst[s] = tf32r((v[s] - mn2) * inv2);
}

// ---------------- kernel 5: L2 conv + output via tf32 mma (q=14 chunks of 4 rows) ----------------
#define A_STR 36
__global__ __launch_bounds__(128, 2) void k_l2mma(float* __restrict__ out) {
    __shared__ float sA[2][32 * A_STR];          // W2 slice, cols 25..31 zero
    __shared__ __align__(16) float sP[2][480];   // 8 pad rows x 60
    __shared__ int wl[32];
    int q = blockIdx.x, b = blockIdx.y;
    int tid = threadIdx.x, wid = tid >> 5, lane = tid & 31;
    int gid = lane >> 2, tig = lane & 3;
    if (tid < 32) wl[tid] = g_fmidx[b * NFM + tid];
    for (int p = tid; p < 2 * 32 * A_STR; p += 128) ((float*)sA)[p] = 0.f;
    __syncthreads();

    int offk[4][2];
    #pragma unroll
    for (int ks = 0; ks < 4; ks++) {
        #pragma unroll
        for (int hh = 0; hh < 2; hh++) {
            int xy = ks * 8 + tig + hh * 4; if (xy > 24) xy = 24;
            int kx = xy / 5, ky = xy - kx * 5;
            offk[ks][hh] = kx * 60 + ky;
        }
    }
    int ntBeg = wid * 7;           // 28 n-tiles, 7 per warp, all valid
    float acc[7][2][4];
    #pragma unroll
    for (int j = 0; j < 7; j++)
        #pragma unroll
        for (int m = 0; m < 2; m++)
            #pragma unroll
            for (int v = 0; v < 4; v++) acc[j][m][v] = 0.f;

    {   // preload i = 0
        int iCh = wl[0];
        unsigned dA = (unsigned)__cvta_generic_to_shared(&sA[0][0]);
        for (int idx = tid; idx < 800; idx += 128) {
            int m = idx / 25, k = idx - m * 25;
            cp4(dA + (unsigned)((m * A_STR + k) * 4),
                g_W2 + ((size_t)wl[m] * NC + iCh) * 25 + k);
        }
        unsigned dP = (unsigned)__cvta_generic_to_shared(&sP[0][0]);
        const float* src = &g_Pad[b][0][0] + q * 240;
        for (int idx = tid; idx < 120; idx += 128)
            cp16(dP + (unsigned)(idx * 16), src + idx * 4);
        cp_commit();
    }
    for (int i = 0; i < 32; i++) {
        int st = i & 1;
        if (i + 1 < 32) {
            int iCh = wl[i + 1];
            unsigned dA = (unsigned)__cvta_generic_to_shared(&sA[st ^ 1][0]);
            for (int idx = tid; idx < 800; idx += 128) {
                int m = idx / 25, k = idx - m * 25;
                cp4(dA + (unsigned)((m * A_STR + k) * 4),
                    g_W2 + ((size_t)wl[m] * NC + iCh) * 25 + k);
            }
            unsigned dP = (unsigned)__cvta_generic_to_shared(&sP[st ^ 1][0]);
            const float* src = &g_Pad[b][i + 1][0] + q * 240;
            for (int idx = tid; idx < 120; idx += 128)
                cp16(dP + (unsigned)(idx * 16), src + idx * 4);
            cp_commit();
            asm volatile("cp.async.wait_group 1;" ::: "memory");
        } else {
            asm volatile("cp.async.wait_group 0;" ::: "memory");
        }
        __syncthreads();
        const float* Ax = &sA[st][0];
        const float* Pz = &sP[st][0];
        unsigned aF[2][4][4];
        #pragma unroll
        for (int mt = 0; mt < 2; mt++)
            #pragma unroll
            for (int ks = 0; ks < 4; ks++) {
                int base = (mt * 16 + gid) * A_STR + ks * 8 + tig;
                aF[mt][ks][0] = __float_as_uint(Ax[base]);
                aF[mt][ks][1] = __float_as_uint(Ax[base + 8 * A_STR]);
                aF[mt][ks][2] = __float_as_uint(Ax[base + 4]);
                aF[mt][ks][3] = __float_as_uint(Ax[base + 8 * A_STR + 4]);
            }
        #pragma unroll
        for (int j = 0; j < 7; j++) {
            int lp = (ntBeg + j) * 8 + gid;        // 0..223
            int r = (lp * 1171) >> 16;             // lp / 56
            int base = lp + r * 4;                 // r*60 + (lp - r*56)
            #pragma unroll
            for (int ks = 0; ks < 4; ks++) {
                unsigned b0 = __float_as_uint(Pz[base + offk[ks][0]]);
                unsigned b1 = __float_as_uint(Pz[base + offk[ks][1]]);
                mma_tf32(acc[j][0], aF[0][ks][0], aF[0][ks][1], aF[0][ks][2],
                         aF[0][ks][3], b0, b1);
                mma_tf32(acc[j][1], aF[1][ks][0], aF[1][ks][1], aF[1][ks][2],
                         aF[1][ks][3], b0, b1);
            }
        }
        __syncthreads();
    }
    const float cmul = 0.1f / 32.0f;
    #pragma unroll
    for (int j = 0; j < 7; j++) {
        int p = q * 224 + (ntBeg + j) * 8 + tig * 2;
        #pragma unroll
        for (int mt = 0; mt < 2; mt++) {
            int fm0 = mt * 16 + gid, fm1 = fm0 + 8;
            const float* ab0 = g_Ab + ((size_t)b * NC + wl[fm0]) * HW;
            const float* ab1 = g_Ab + ((size_t)b * NC + wl[fm1]) * HW;
            float* o0 = out + ((size_t)b * NFM + fm0) * HW;
            float* o1 = out + ((size_t)b * NFM + fm1) * HW;
            o0[p]     = ab0[p]     + cmul * acc[j][mt][0];
            o0[p + 1] = ab0[p + 1] + cmul * acc[j][mt][1];
            o1[p]     = ab1[p]     + cmul * acc[j][mt][2];
            o1[p + 1] = ab1[p + 1] + cmul * acc[j][mt][3];
        }
    }
}

extern "C" void kernel_launch(void* const* d_in, const int* in_sizes, int n_in,
                              void* d_out, int out_size) {
    const float* A     = (const float*)d_in[0];
    const float* K     = (const float*)d_in[1];
    const float* noise = (const float*)d_in[2];
    float* out = (float*)d_out;

    cudaFuncSetAttribute(k_kchange, cudaFuncAttributeMaxDynamicSharedMemorySize, KC_SMEM);

    k_zero<<<400, 1024>>>();
    k_ab<<<512, 256>>>(A, noise);
    k_winners<<<1, 512>>>();
    k_pad<<<dim3(16, 32), 256>>>();
    k_kchange<<<dim3(16, 16), 256, KC_SMEM>>>();
    k_combine<<<64, 256>>>(K);
    k_l2mma<<<dim3(14, 16), 128>>>(out);
}